// round 1
// baseline (speedup 1.0000x reference)
#include <cuda_runtime.h>
#include <math.h>

#define BATCH 4
#define HEADS 16
#define SEQ   2048
#define DIM   1024
#define DHEAD 64
#define SCALE 0.03125f            // DIM^-0.5 (module uses dim, not dim_head)

#define MTOT  (BATCH*SEQ)         // 8192
#define QKVN  (3*HEADS*DHEAD)     // 3072

// Scratch (device globals: no allocations allowed)
__device__ float g_q[BATCH*HEADS*SEQ*DHEAD];   // [b,h,n,d], pre-scaled
__device__ float g_k[BATCH*HEADS*SEQ*DHEAD];
__device__ float g_v[BATCH*HEADS*SEQ*DHEAD];
__device__ float g_att[MTOT*DIM];              // [b*n, h*d]

// ---------------------------------------------------------------------------
// Tiled fp32 GEMM: 128x128 tile, BK=16, 256 threads, 8x8 per-thread microtile.
// MODE 0: C = x @ w_qkv, epilogue scatters into g_q (scaled)/g_k/g_v.
// MODE 1: C = g_att @ w_out + bias, written to output.
// ---------------------------------------------------------------------------
template<int NCOLS, int KDIM, int MODE>
__global__ __launch_bounds__(256) void gemm_kernel(
    const float* __restrict__ A, const float* __restrict__ B,
    const float* __restrict__ bias, float* __restrict__ C)
{
    __shared__ float As[16][132];   // transposed A tile, padded
    __shared__ float Bs[16][128];

    const float* Ap = (MODE == 1) ? (const float*)g_att : A;

    const int tid  = threadIdx.x;
    const int row0 = blockIdx.y * 128;
    const int col0 = blockIdx.x * 128;

    const int ar = tid >> 2;           // 0..63 (two passes cover 128 rows)
    const int ak = (tid & 3) << 2;     // 0,4,8,12
    const int br = tid >> 5;           // 0..7  (two passes cover 16 rows)
    const int bc = (tid & 31) << 2;

    const int trow = (tid >> 4) << 3;
    const int tcol = (tid & 15) << 3;

    float acc[8][8] = {};

    for (int k0 = 0; k0 < KDIM; k0 += 16) {
        #pragma unroll
        for (int p = 0; p < 2; p++) {
            int r = ar + p * 64;
            float4 v = *(const float4*)(Ap + (size_t)(row0 + r) * KDIM + k0 + ak);
            As[ak + 0][r] = v.x; As[ak + 1][r] = v.y;
            As[ak + 2][r] = v.z; As[ak + 3][r] = v.w;
        }
        #pragma unroll
        for (int p = 0; p < 2; p++) {
            int r = br + p * 8;
            *(float4*)&Bs[r][bc] =
                *(const float4*)(B + (size_t)(k0 + r) * NCOLS + col0 + bc);
        }
        __syncthreads();

        #pragma unroll
        for (int kk = 0; kk < 16; kk++) {
            float a0[8], b0[8];
            *(float4*)&a0[0] = *(const float4*)&As[kk][trow];
            *(float4*)&a0[4] = *(const float4*)&As[kk][trow + 4];
            *(float4*)&b0[0] = *(const float4*)&Bs[kk][tcol];
            *(float4*)&b0[4] = *(const float4*)&Bs[kk][tcol + 4];
            #pragma unroll
            for (int i = 0; i < 8; i++)
                #pragma unroll
                for (int j = 0; j < 8; j++)
                    acc[i][j] = fmaf(a0[i], b0[j], acc[i][j]);
        }
        __syncthreads();
    }

    if (MODE == 0) {
        // Scatter into per-head Q/K/V buffers; fold softmax scale into Q.
        #pragma unroll
        for (int i = 0; i < 8; i++) {
            int row = row0 + trow + i;
            int b = row >> 11;          // / SEQ
            int n = row & (SEQ - 1);
            #pragma unroll
            for (int j = 0; j < 8; j++) {
                int col  = col0 + tcol + j;
                int part = col >> 10;           // 0=Q 1=K 2=V (tile never straddles)
                int w    = col & 1023;
                int h    = w >> 6;
                int d    = w & 63;
                size_t idx = ((size_t)((b * HEADS + h) * SEQ + n)) * DHEAD + d;
                float v = acc[i][j];
                if      (part == 0) g_q[idx] = v * SCALE;
                else if (part == 1) g_k[idx] = v;
                else                g_v[idx] = v;
            }
        }
    } else {
        #pragma unroll
        for (int i = 0; i < 8; i++) {
            int row = row0 + trow + i;
            #pragma unroll
            for (int j = 0; j < 8; j += 4) {
                int col = col0 + tcol + j;
                float4 v;
                v.x = acc[i][j + 0] + bias[col + 0];
                v.y = acc[i][j + 1] + bias[col + 1];
                v.z = acc[i][j + 2] + bias[col + 2];
                v.w = acc[i][j + 3] + bias[col + 3];
                *(float4*)(C + (size_t)row * NCOLS + col) = v;
            }
        }
    }
}

// ---------------------------------------------------------------------------
// Flash attention: one block = one (b,h) and a 64-row Q tile; KV tiles of 32.
// Q and K stored d-major in smem (conflict-free float4 reads); P padded +1.
// 128 threads. Online softmax; accumulators in registers.
// ---------------------------------------------------------------------------
__global__ __launch_bounds__(128) void attn_kernel()
{
    __shared__ float Qt[64][64];    // [d][i]
    __shared__ float Kt[64][32];    // [d][j]
    __shared__ float Vs[32][64];    // [j][d]
    __shared__ float Ps[64][33];    // [i][j], padded
    __shared__ float alpha_s[64];
    __shared__ float l_s[64];

    const int tid = threadIdx.x;
    const int bh  = blockIdx.y;
    const int q0  = blockIdx.x * 64;

    const float* Qp = g_q + ((size_t)bh * SEQ + q0) * DHEAD;
    const float* Kp = g_k + (size_t)bh * SEQ * DHEAD;
    const float* Vp = g_v + (size_t)bh * SEQ * DHEAD;

    // Load Q tile transposed (d-major)
    #pragma unroll
    for (int r = 0; r < 8; r++) {
        int lin = tid + r * 128;
        int i = lin >> 4;
        int c = (lin & 15) << 2;
        float4 v = *(const float4*)(Qp + i * DHEAD + c);
        Qt[c + 0][i] = v.x; Qt[c + 1][i] = v.y;
        Qt[c + 2][i] = v.z; Qt[c + 3][i] = v.w;
    }

    // S-phase mapping: 16x8 threads, each computes 4 rows x 4 cols of S
    const int ty = tid >> 3, tx = tid & 7;
    const int i0 = ty << 2, j0 = tx << 2;
    // O-phase mapping: 2 threads per row, 32 d each
    const int io = tid >> 1, dh0 = (tid & 1) << 5;

    float m_prev[4], l_acc[4];
    #pragma unroll
    for (int ii = 0; ii < 4; ii++) { m_prev[ii] = -1e30f; l_acc[ii] = 0.f; }
    float o[32];
    #pragma unroll
    for (int d = 0; d < 32; d++) o[d] = 0.f;

    for (int kv0 = 0; kv0 < SEQ; kv0 += 32) {
        __syncthreads();   // prior-iter O-phase readers done before K/V overwrite
        #pragma unroll
        for (int r = 0; r < 4; r++) {
            int lin = tid + r * 128;
            int j = lin >> 4;
            int c = (lin & 15) << 2;
            float4 kv = *(const float4*)(Kp + (size_t)(kv0 + j) * DHEAD + c);
            Kt[c + 0][j] = kv.x; Kt[c + 1][j] = kv.y;
            Kt[c + 2][j] = kv.z; Kt[c + 3][j] = kv.w;
            *(float4*)&Vs[j][c] = *(const float4*)(Vp + (size_t)(kv0 + j) * DHEAD + c);
        }
        __syncthreads();

        // S = Q @ K^T  (Q already scaled)
        float s[4][4] = {};
        #pragma unroll
        for (int d = 0; d < 64; d++) {
            float qa[4], ka[4];
            *(float4*)qa = *(const float4*)&Qt[d][i0];
            *(float4*)ka = *(const float4*)&Kt[d][j0];
            #pragma unroll
            for (int ii = 0; ii < 4; ii++)
                #pragma unroll
                for (int jj = 0; jj < 4; jj++)
                    s[ii][jj] = fmaf(qa[ii], ka[jj], s[ii][jj]);
        }

        // Online softmax (row reduce across the 8 tx-lanes)
        #pragma unroll
        for (int ii = 0; ii < 4; ii++) {
            float rm = fmaxf(fmaxf(s[ii][0], s[ii][1]), fmaxf(s[ii][2], s[ii][3]));
            rm = fmaxf(rm, __shfl_xor_sync(0xffffffffu, rm, 1));
            rm = fmaxf(rm, __shfl_xor_sync(0xffffffffu, rm, 2));
            rm = fmaxf(rm, __shfl_xor_sync(0xffffffffu, rm, 4));
            float mn = fmaxf(m_prev[ii], rm);
            float sum = 0.f;
            #pragma unroll
            for (int jj = 0; jj < 4; jj++) {
                float p = __expf(s[ii][jj] - mn);
                s[ii][jj] = p;
                sum += p;
            }
            sum += __shfl_xor_sync(0xffffffffu, sum, 1);
            sum += __shfl_xor_sync(0xffffffffu, sum, 2);
            sum += __shfl_xor_sync(0xffffffffu, sum, 4);
            float al = __expf(m_prev[ii] - mn);
            l_acc[ii] = l_acc[ii] * al + sum;
            m_prev[ii] = mn;
            if (tx == 0) alpha_s[i0 + ii] = al;
            #pragma unroll
            for (int jj = 0; jj < 4; jj++) Ps[i0 + ii][j0 + jj] = s[ii][jj];
        }
        __syncthreads();

        // O = alpha*O + P @ V
        float a = alpha_s[io];
        #pragma unroll
        for (int d = 0; d < 32; d++) o[d] *= a;
        #pragma unroll
        for (int j = 0; j < 32; j++) {
            float p = Ps[io][j];
            #pragma unroll
            for (int q = 0; q < 8; q++) {
                float va[4];
                *(float4*)va = *(const float4*)&Vs[j][dh0 + q * 4];
                o[q * 4 + 0] = fmaf(p, va[0], o[q * 4 + 0]);
                o[q * 4 + 1] = fmaf(p, va[1], o[q * 4 + 1]);
                o[q * 4 + 2] = fmaf(p, va[2], o[q * 4 + 2]);
                o[q * 4 + 3] = fmaf(p, va[3], o[q * 4 + 3]);
            }
        }
    }

    if (tx == 0) {
        #pragma unroll
        for (int ii = 0; ii < 4; ii++) l_s[i0 + ii] = l_acc[ii];
    }
    __syncthreads();

    float inv = 1.f / l_s[io];
    int b = bh >> 4, h = bh & 15;
    float* dst = g_att + ((size_t)(b * SEQ + q0 + io)) * DIM + h * DHEAD + dh0;
    #pragma unroll
    for (int q = 0; q < 8; q++) {
        float4 v;
        v.x = o[q * 4 + 0] * inv;
        v.y = o[q * 4 + 1] * inv;
        v.z = o[q * 4 + 2] * inv;
        v.w = o[q * 4 + 3] * inv;
        *(float4*)(dst + q * 4) = v;
    }
}

// ---------------------------------------------------------------------------
extern "C" void kernel_launch(void* const* d_in, const int* in_sizes, int n_in,
                              void* d_out, int out_size)
{
    const float* x     = (const float*)d_in[0];
    const float* w_qkv = (const float*)d_in[1];
    const float* w_out = (const float*)d_in[2];
    const float* b_out = (const float*)d_in[3];
    float* out = (float*)d_out;
    (void)in_sizes; (void)n_in; (void)out_size;

    dim3 gq(QKVN / 128, MTOT / 128);          // 24 x 64
    gemm_kernel<QKVN, DIM, 0><<<gq, 256>>>(x, w_qkv, nullptr, nullptr);

    dim3 ga(SEQ / 64, BATCH * HEADS);         // 32 x 64
    attn_kernel<<<ga, 128>>>();

    dim3 go(DIM / 128, MTOT / 128);           // 8 x 64
    gemm_kernel<DIM, DIM, 1><<<go, 256>>>(nullptr, w_out, b_out, out);
}

// round 4
// speedup vs baseline: 1.1854x; 1.1854x over previous
#include <cuda_runtime.h>
#include <cuda_bf16.h>
#include <cstdint>
#include <math.h>

#define BATCH 4
#define HEADS 16
#define SEQ   2048
#define DIM   1024
#define DHEAD 64
#define SCALE 0.03125f            // DIM^-0.5 (module uses dim, not dim_head)

#define MTOT  (BATCH*SEQ)         // 8192
#define QKVN  (3*HEADS*DHEAD)     // 3072

// Scratch (device globals: no allocations allowed)
__device__ float g_q[BATCH*HEADS*SEQ*DHEAD];   // [b,h,n,d], pre-scaled
__device__ float g_k[BATCH*HEADS*SEQ*DHEAD];
__device__ float g_v[BATCH*HEADS*SEQ*DHEAD];
__device__ float g_att[MTOT*DIM];              // [b*n, h*d]
__device__ float g_wqkvT[QKVN*DIM];            // [3072,1024] = w_qkv^T
__device__ float g_woutT[DIM*DIM];             // [1024,1024] = w_out^T

// ---------------------------------------------------------------------------
// Portable tensor-core helpers (mma.sync + ldmatrix; no tcgen05)
// ---------------------------------------------------------------------------
__device__ __forceinline__ uint32_t smem_u32(const void* p) {
    uint32_t a;
    asm("{ .reg .u64 t; cvta.to.shared.u64 t, %1; cvt.u32.u64 %0, t; }"
        : "=r"(a) : "l"(p));
    return a;
}
__device__ __forceinline__ void ldsm4(uint32_t* r, uint32_t addr) {
    asm volatile("ldmatrix.sync.aligned.m8n8.x4.shared.b16 {%0,%1,%2,%3}, [%4];"
                 : "=r"(r[0]), "=r"(r[1]), "=r"(r[2]), "=r"(r[3]) : "r"(addr));
}
// b0 = k0..7 plane, b1 = k8..15 plane for the SAME n-block (non-contiguous regs!)
__device__ __forceinline__ void mma_bf16(float* c, const uint32_t* a,
                                         uint32_t b0, uint32_t b1) {
    asm volatile("mma.sync.aligned.m16n8k16.row.col.f32.bf16.bf16.f32 "
                 "{%0,%1,%2,%3}, {%4,%5,%6,%7}, {%8,%9}, {%0,%1,%2,%3};"
                 : "+f"(c[0]), "+f"(c[1]), "+f"(c[2]), "+f"(c[3])
                 : "r"(a[0]), "r"(a[1]), "r"(a[2]), "r"(a[3]),
                   "r"(b0), "r"(b1));
}
__device__ __forceinline__ void sts128u(uint32_t addr, const uint32_t* v) {
    asm volatile("st.shared.v4.b32 [%0], {%1,%2,%3,%4};"
                 :: "r"(addr), "r"(v[0]), "r"(v[1]), "r"(v[2]), "r"(v[3]) : "memory");
}

// Convert 16 fp32 -> bf16 hi plane (32B) + bf16 mid plane (32B), store to smem.
// Mid plane lives at hi_addr + PLANE_OFS.
#define PLANE_OFS 10240u
__device__ __forceinline__ void cvt_sts16(const float4* s, uint32_t hi_addr) {
    uint32_t hi[8], mid[8];
    const float* f = (const float*)s;
    #pragma unroll
    for (int i = 0; i < 8; i++) {
        float a = f[2*i], b = f[2*i+1];
        __nv_bfloat162 h = __floats2bfloat162_rn(a, b);
        float ra = a - __bfloat162float(h.x);
        float rb = b - __bfloat162float(h.y);
        __nv_bfloat162 m = __floats2bfloat162_rn(ra, rb);
        hi[i]  = *(const uint32_t*)&h;
        mid[i] = *(const uint32_t*)&m;
    }
    sts128u(hi_addr,                  hi);
    sts128u(hi_addr + 16,             hi + 4);
    sts128u(hi_addr + PLANE_OFS,      mid);
    sts128u(hi_addr + PLANE_OFS + 16, mid + 4);
}

// ---------------------------------------------------------------------------
// Weight transpose: dst[c*R + r] = src[r*C + c]
// ---------------------------------------------------------------------------
template<int R, int C, int WHICH>
__global__ __launch_bounds__(256) void transpose_kernel(const float* __restrict__ src)
{
    __shared__ float t[32][33];
    float* dst = WHICH ? g_woutT : g_wqkvT;
    int c0 = blockIdx.x * 32, r0 = blockIdx.y * 32;
    #pragma unroll
    for (int i = threadIdx.y; i < 32; i += 8)
        t[i][threadIdx.x] = src[(size_t)(r0 + i) * C + c0 + threadIdx.x];
    __syncthreads();
    #pragma unroll
    for (int i = threadIdx.y; i < 32; i += 8)
        dst[(size_t)(c0 + i) * R + r0 + threadIdx.x] = t[threadIdx.x][i];
}

// ---------------------------------------------------------------------------
// mma.sync bf16 split GEMM. CTA tile 128x128, KC=32, 256 threads (8 warps,
// each 64x32 via m16n8k16). A: rows of C; B: K-major (pre-transposed weights).
// Smem layout per buffer (pitch 80B/row, conflict-free for ldmatrix):
//   A_hi @ 0, A_mid @ 10240, B_hi @ 20480, B_mid @ 30720   (40960 B / buffer)
// 3 mma passes: Ah*Bh + Ah*Bm + Am*Bh  (fp32 accum in regs).
// MODE 0: x @ w_qkv -> scatter g_q(*SCALE)/g_k/g_v.  MODE 1: g_att @ w_out + b.
// ---------------------------------------------------------------------------
#define GEMM_DYNSMEM (2*40960)

template<int MODE>
__global__ __launch_bounds__(256, 1) void mma_gemm(
    const float* __restrict__ Ain, const float* __restrict__ bias,
    float* __restrict__ C)
{
    extern __shared__ char sm[];
    const float* A  = (MODE == 1) ? (const float*)g_att : Ain;
    const float* Bt = (MODE == 1) ? (const float*)g_woutT : (const float*)g_wqkvT;
    const int K = 1024;

    const int tid  = threadIdx.x;
    const int lane = tid & 31, wid = tid >> 5;
    const int warp_m = (wid >> 2) * 64;      // 0 or 64
    const int warp_n = (wid & 3) * 32;       // 0..96
    const int row0 = blockIdx.y * 128;
    const int col0 = blockIdx.x * 128;

    const uint32_t smb = smem_u32(sm);

    // Loader: thread -> (row, k-half). 256 threads cover 128 rows x 2 halves.
    const int lrow  = tid >> 1;
    const int lhalf = tid & 1;
    const float* gA = A  + (size_t)(row0 + lrow) * K + lhalf * 16;
    const float* gB = Bt + (size_t)(col0 + lrow) * K + lhalf * 16;
    const uint32_t stA = (uint32_t)(lrow * 80 + lhalf * 32);          // A_hi ofs
    const uint32_t stB = stA + 20480u;                                // B_hi ofs

    // ldmatrix per-lane address pieces:
    //   lanes 0..15 -> rows 0..15 @ k-bytes 0   (matrices m0/m1 = k0..7)
    //   lanes 16..31 -> rows 0..15 @ k-bytes 16 (matrices m2/m3 = k8..15)
    const uint32_t lm_row = (uint32_t)(lane & 15);
    const uint32_t lm_col = (lane & 16) ? 16u : 0u;
    const uint32_t aofs = (uint32_t)(warp_m + lm_row) * 80 + lm_col;            // A_hi
    const uint32_t bofs = 20480u + (uint32_t)(warp_n + lm_row) * 80 + lm_col;   // B_hi

    float acc[4][4][4];
    #pragma unroll
    for (int t = 0; t < 4; t++)
        #pragma unroll
        for (int j = 0; j < 4; j++)
            #pragma unroll
            for (int r = 0; r < 4; r++) acc[t][j][r] = 0.f;

    float4 stg[8];
    #pragma unroll
    for (int i = 0; i < 4; i++) stg[i]     = *(const float4*)(gA + i * 4);
    #pragma unroll
    for (int i = 0; i < 4; i++) stg[4 + i] = *(const float4*)(gB + i * 4);
    cvt_sts16(&stg[0], smb + stA);
    cvt_sts16(&stg[4], smb + stB);
    __syncthreads();

    for (int c = 0; c < 32; ++c) {
        const uint32_t buf = smb + (uint32_t)(c & 1) * 40960u;
        if (c < 31) {
            const float* pA = gA + (c + 1) * 32;
            const float* pB = gB + (c + 1) * 32;
            #pragma unroll
            for (int i = 0; i < 4; i++) stg[i]     = *(const float4*)(pA + i * 4);
            #pragma unroll
            for (int i = 0; i < 4; i++) stg[4 + i] = *(const float4*)(pB + i * 4);
        }
        #pragma unroll
        for (int ks = 0; ks < 2; ++ks) {
            uint32_t Ah[4][4], Am[4][4], Bh[2][4], Bm[2][4];
            #pragma unroll
            for (int t = 0; t < 4; t++) {
                uint32_t ad = buf + aofs + (uint32_t)(t * 16 * 80 + ks * 32);
                ldsm4(Ah[t], ad);
                ldsm4(Am[t], ad + PLANE_OFS);
            }
            #pragma unroll
            for (int u = 0; u < 2; u++) {
                uint32_t bd = buf + bofs + (uint32_t)(u * 16 * 80 + ks * 32);
                ldsm4(Bh[u], bd);
                ldsm4(Bm[u], bd + PLANE_OFS);
            }
            // B x4 matrices: m0=(n0-7,k0-7) m1=(n8-15,k0-7) m2=(n0-7,k8-15) m3=(n8-15,k8-15)
            // => fragment for n-block (j&1): {B[j&1], B[(j&1)+2]}
            #pragma unroll
            for (int t = 0; t < 4; t++)
                #pragma unroll
                for (int j = 0; j < 4; j++) {
                    const int u = j >> 1, s = j & 1;
                    mma_bf16(acc[t][j], Ah[t], Bh[u][s], Bh[u][s + 2]);
                    mma_bf16(acc[t][j], Ah[t], Bm[u][s], Bm[u][s + 2]);
                    mma_bf16(acc[t][j], Am[t], Bh[u][s], Bh[u][s + 2]);
                }
        }
        if (c < 31) {
            const uint32_t nb = smb + (uint32_t)((c + 1) & 1) * 40960u;
            cvt_sts16(&stg[0], nb + stA);
            cvt_sts16(&stg[4], nb + stB);
        }
        __syncthreads();
    }

    // Epilogue from register accumulators.
    const int g  = lane >> 2;
    const int tg = lane & 3;
    #pragma unroll
    for (int t = 0; t < 4; t++) {
        const int rowA = row0 + warp_m + t * 16 + g;      // and rowA+8
        #pragma unroll
        for (int j = 0; j < 4; j++) {
            const int cg = col0 + warp_n + j * 8 + 2 * tg;
            float2 lo = make_float2(acc[t][j][0], acc[t][j][1]);   // row rowA
            float2 hi = make_float2(acc[t][j][2], acc[t][j][3]);   // row rowA+8
            if (MODE == 0) {
                const int part = cg >> 10;
                const int w = cg & 1023;
                const int h = w >> 6, d = w & 63;
                #pragma unroll
                for (int rr = 0; rr < 2; rr++) {
                    const int row = rowA + rr * 8;
                    const int b = row >> 11, n = row & (SEQ - 1);
                    const size_t idx = ((size_t)((b * HEADS + h) * SEQ + n)) * DHEAD + d;
                    float2 v = rr ? hi : lo;
                    if (part == 0) {
                        v.x *= SCALE; v.y *= SCALE;
                        *(float2*)(g_q + idx) = v;
                    } else if (part == 1) {
                        *(float2*)(g_k + idx) = v;
                    } else {
                        *(float2*)(g_v + idx) = v;
                    }
                }
            } else {
                const float bx = bias[cg], by = bias[cg + 1];
                lo.x += bx; lo.y += by;
                hi.x += bx; hi.y += by;
                *(float2*)(C + (size_t)rowA * DIM + cg) = lo;
                *(float2*)(C + (size_t)(rowA + 8) * DIM + cg) = hi;
            }
        }
    }
}

// ---------------------------------------------------------------------------
// Flash attention (SIMT fp32, unchanged from passing baseline)
// ---------------------------------------------------------------------------
__global__ __launch_bounds__(128) void attn_kernel()
{
    __shared__ float Qt[64][64];    // [d][i]
    __shared__ float Kt[64][32];    // [d][j]
    __shared__ float Vs[32][64];    // [j][d]
    __shared__ float Ps[64][33];    // [i][j], padded
    __shared__ float alpha_s[64];
    __shared__ float l_s[64];

    const int tid = threadIdx.x;
    const int bh  = blockIdx.y;
    const int q0  = blockIdx.x * 64;

    const float* Qp = g_q + ((size_t)bh * SEQ + q0) * DHEAD;
    const float* Kp = g_k + (size_t)bh * SEQ * DHEAD;
    const float* Vp = g_v + (size_t)bh * SEQ * DHEAD;

    #pragma unroll
    for (int r = 0; r < 8; r++) {
        int lin = tid + r * 128;
        int i = lin >> 4;
        int c = (lin & 15) << 2;
        float4 v = *(const float4*)(Qp + i * DHEAD + c);
        Qt[c + 0][i] = v.x; Qt[c + 1][i] = v.y;
        Qt[c + 2][i] = v.z; Qt[c + 3][i] = v.w;
    }

    const int ty = tid >> 3, tx = tid & 7;
    const int i0 = ty << 2, j0 = tx << 2;
    const int io = tid >> 1, dh0 = (tid & 1) << 5;

    float m_prev[4], l_acc[4];
    #pragma unroll
    for (int ii = 0; ii < 4; ii++) { m_prev[ii] = -1e30f; l_acc[ii] = 0.f; }
    float o[32];
    #pragma unroll
    for (int d = 0; d < 32; d++) o[d] = 0.f;

    for (int kv0 = 0; kv0 < SEQ; kv0 += 32) {
        __syncthreads();
        #pragma unroll
        for (int r = 0; r < 4; r++) {
            int lin = tid + r * 128;
            int j = lin >> 4;
            int c = (lin & 15) << 2;
            float4 kv = *(const float4*)(Kp + (size_t)(kv0 + j) * DHEAD + c);
            Kt[c + 0][j] = kv.x; Kt[c + 1][j] = kv.y;
            Kt[c + 2][j] = kv.z; Kt[c + 3][j] = kv.w;
            *(float4*)&Vs[j][c] = *(const float4*)(Vp + (size_t)(kv0 + j) * DHEAD + c);
        }
        __syncthreads();

        float s[4][4] = {};
        #pragma unroll
        for (int d = 0; d < 64; d++) {
            float qa[4], ka[4];
            *(float4*)qa = *(const float4*)&Qt[d][i0];
            *(float4*)ka = *(const float4*)&Kt[d][j0];
            #pragma unroll
            for (int ii = 0; ii < 4; ii++)
                #pragma unroll
                for (int jj = 0; jj < 4; jj++)
                    s[ii][jj] = fmaf(qa[ii], ka[jj], s[ii][jj]);
        }

        #pragma unroll
        for (int ii = 0; ii < 4; ii++) {
            float rm = fmaxf(fmaxf(s[ii][0], s[ii][1]), fmaxf(s[ii][2], s[ii][3]));
            rm = fmaxf(rm, __shfl_xor_sync(0xffffffffu, rm, 1));
            rm = fmaxf(rm, __shfl_xor_sync(0xffffffffu, rm, 2));
            rm = fmaxf(rm, __shfl_xor_sync(0xffffffffu, rm, 4));
            float mn = fmaxf(m_prev[ii], rm);
            float sum = 0.f;
            #pragma unroll
            for (int jj = 0; jj < 4; jj++) {
                float p = __expf(s[ii][jj] - mn);
                s[ii][jj] = p;
                sum += p;
            }
            sum += __shfl_xor_sync(0xffffffffu, sum, 1);
            sum += __shfl_xor_sync(0xffffffffu, sum, 2);
            sum += __shfl_xor_sync(0xffffffffu, sum, 4);
            float al = __expf(m_prev[ii] - mn);
            l_acc[ii] = l_acc[ii] * al + sum;
            m_prev[ii] = mn;
            if (tx == 0) alpha_s[i0 + ii] = al;
            #pragma unroll
            for (int jj = 0; jj < 4; jj++) Ps[i0 + ii][j0 + jj] = s[ii][jj];
        }
        __syncthreads();

        float a = alpha_s[io];
        #pragma unroll
        for (int d = 0; d < 32; d++) o[d] *= a;
        #pragma unroll
        for (int j = 0; j < 32; j++) {
            float p = Ps[io][j];
            #pragma unroll
            for (int q = 0; q < 8; q++) {
                float va[4];
                *(float4*)va = *(const float4*)&Vs[j][dh0 + q * 4];
                o[q * 4 + 0] = fmaf(p, va[0], o[q * 4 + 0]);
                o[q * 4 + 1] = fmaf(p, va[1], o[q * 4 + 1]);
                o[q * 4 + 2] = fmaf(p, va[2], o[q * 4 + 2]);
                o[q * 4 + 3] = fmaf(p, va[3], o[q * 4 + 3]);
            }
        }
    }

    if (tx == 0) {
        #pragma unroll
        for (int ii = 0; ii < 4; ii++) l_s[i0 + ii] = l_acc[ii];
    }
    __syncthreads();

    float inv = 1.f / l_s[io];
    int b = bh >> 4, h = bh & 15;
    float* dst = g_att + ((size_t)(b * SEQ + q0 + io)) * DIM + h * DHEAD + dh0;
    #pragma unroll
    for (int q = 0; q < 8; q++) {
        float4 v;
        v.x = o[q * 4 + 0] * inv;
        v.y = o[q * 4 + 1] * inv;
        v.z = o[q * 4 + 2] * inv;
        v.w = o[q * 4 + 3] * inv;
        *(float4*)(dst + q * 4) = v;
    }
}

// ---------------------------------------------------------------------------
extern "C" void kernel_launch(void* const* d_in, const int* in_sizes, int n_in,
                              void* d_out, int out_size)
{
    const float* x     = (const float*)d_in[0];
    const float* w_qkv = (const float*)d_in[1];
    const float* w_out = (const float*)d_in[2];
    const float* b_out = (const float*)d_in[3];
    float* out = (float*)d_out;
    (void)in_sizes; (void)n_in; (void)out_size;

    cudaFuncSetAttribute(mma_gemm<0>, cudaFuncAttributeMaxDynamicSharedMemorySize, GEMM_DYNSMEM);
    cudaFuncSetAttribute(mma_gemm<1>, cudaFuncAttributeMaxDynamicSharedMemorySize, GEMM_DYNSMEM);

    // Transpose weights (K-major operands)
    transpose_kernel<DIM, QKVN, 0><<<dim3(QKVN / 32, DIM / 32), dim3(32, 8)>>>(w_qkv);
    transpose_kernel<DIM, DIM, 1><<<dim3(DIM / 32, DIM / 32), dim3(32, 8)>>>(w_out);

    // QKV projection (mma.sync bf16-split)
    dim3 gq(QKVN / 128, MTOT / 128);          // 24 x 64
    mma_gemm<0><<<gq, 256, GEMM_DYNSMEM>>>(x, nullptr, nullptr);

    // Flash attention (SIMT fp32)
    dim3 ga(SEQ / 64, BATCH * HEADS);         // 32 x 64
    attn_kernel<<<ga, 128>>>();

    // Output projection (mma.sync bf16-split) + bias
    dim3 go(DIM / 128, MTOT / 128);           // 8 x 64
    mma_gemm<1><<<go, 256, GEMM_DYNSMEM>>>(nullptr, b_out, out);
}

// round 5
// speedup vs baseline: 3.5124x; 2.9632x over previous
#include <cuda_runtime.h>
#include <cuda_bf16.h>
#include <cstdint>
#include <math.h>

#define BATCH 4
#define HEADS 16
#define SEQ   2048
#define DIM   1024
#define DHEAD 64
#define LOG2E 1.4426950408889634f
#define QSCALE (0.03125f * LOG2E)     // DIM^-0.5 * log2(e), folded into Q

#define MTOT  (BATCH*SEQ)         // 8192
#define QKVN  (3*HEADS*DHEAD)     // 3072

// Scratch (device globals: no allocations allowed)
__device__ float g_q[BATCH*HEADS*SEQ*DHEAD];   // [b,h,n,d], pre-scaled by QSCALE
__device__ float g_k[BATCH*HEADS*SEQ*DHEAD];
__device__ float g_v[BATCH*HEADS*SEQ*DHEAD];
__device__ float g_att[MTOT*DIM];              // [b*n, h*d]
__device__ float g_wqkvT[QKVN*DIM];            // w_qkv^T
__device__ float g_woutT[DIM*DIM];             // w_out^T

// ---------------------------------------------------------------------------
// Portable tensor-core helpers (mma.sync + ldmatrix)
// ---------------------------------------------------------------------------
__device__ __forceinline__ uint32_t smem_u32(const void* p) {
    uint32_t a;
    asm("{ .reg .u64 t; cvta.to.shared.u64 t, %1; cvt.u32.u64 %0, t; }"
        : "=r"(a) : "l"(p));
    return a;
}
__device__ __forceinline__ void ldsm4(uint32_t* r, uint32_t addr) {
    asm volatile("ldmatrix.sync.aligned.m8n8.x4.shared.b16 {%0,%1,%2,%3}, [%4];"
                 : "=r"(r[0]), "=r"(r[1]), "=r"(r[2]), "=r"(r[3]) : "r"(addr));
}
__device__ __forceinline__ void ldsm4t(uint32_t* r, uint32_t addr) {
    asm volatile("ldmatrix.sync.aligned.m8n8.x4.trans.shared.b16 {%0,%1,%2,%3}, [%4];"
                 : "=r"(r[0]), "=r"(r[1]), "=r"(r[2]), "=r"(r[3]) : "r"(addr));
}
// b0 = k0..7 plane, b1 = k8..15 plane for the SAME n-block.
__device__ __forceinline__ void mma_bf16(float* c, const uint32_t* a,
                                         uint32_t b0, uint32_t b1) {
    asm volatile("mma.sync.aligned.m16n8k16.row.col.f32.bf16.bf16.f32 "
                 "{%0,%1,%2,%3}, {%4,%5,%6,%7}, {%8,%9}, {%0,%1,%2,%3};"
                 : "+f"(c[0]), "+f"(c[1]), "+f"(c[2]), "+f"(c[3])
                 : "r"(a[0]), "r"(a[1]), "r"(a[2]), "r"(a[3]),
                   "r"(b0), "r"(b1));
}
__device__ __forceinline__ void sts128u(uint32_t addr, const uint32_t* v) {
    asm volatile("st.shared.v4.b32 [%0], {%1,%2,%3,%4};"
                 :: "r"(addr), "r"(v[0]), "r"(v[1]), "r"(v[2]), "r"(v[3]) : "memory");
}
__device__ __forceinline__ float ex2(float x) {
    float y;
    asm("ex2.approx.ftz.f32 %0, %1;" : "=f"(y) : "f"(x));
    return y;
}
// fp32 pair -> packed bf16x2 hi + bf16x2 mid
__device__ __forceinline__ void cvt2(float x, float y, uint32_t& h, uint32_t& m) {
    __nv_bfloat162 hh = __floats2bfloat162_rn(x, y);
    float rx = x - __bfloat162float(hh.x);
    float ry = y - __bfloat162float(hh.y);
    __nv_bfloat162 mm = __floats2bfloat162_rn(rx, ry);
    h = *(const uint32_t*)&hh;
    m = *(const uint32_t*)&mm;
}
// 16 fp32 -> 32B bf16 hi + 32B bf16 mid planes (mid at +pofs)
__device__ __forceinline__ void cvt_sts16p(const float4* s, uint32_t hi_addr, uint32_t pofs) {
    uint32_t hi[8], mid[8];
    const float* f = (const float*)s;
    #pragma unroll
    for (int i = 0; i < 8; i++) {
        cvt2(f[2*i], f[2*i+1], hi[i], mid[i]);
    }
    sts128u(hi_addr,              hi);
    sts128u(hi_addr + 16,         hi + 4);
    sts128u(hi_addr + pofs,       mid);
    sts128u(hi_addr + pofs + 16,  mid + 4);
}

// ---------------------------------------------------------------------------
// Weight transpose: dst[c*R + r] = src[r*C + c]
// ---------------------------------------------------------------------------
template<int R, int C, int WHICH>
__global__ __launch_bounds__(256) void transpose_kernel(const float* __restrict__ src)
{
    __shared__ float t[32][33];
    float* dst = WHICH ? g_woutT : g_wqkvT;
    int c0 = blockIdx.x * 32, r0 = blockIdx.y * 32;
    #pragma unroll
    for (int i = threadIdx.y; i < 32; i += 8)
        t[i][threadIdx.x] = src[(size_t)(r0 + i) * C + c0 + threadIdx.x];
    __syncthreads();
    #pragma unroll
    for (int i = threadIdx.y; i < 32; i += 8)
        dst[(size_t)(c0 + i) * R + r0 + threadIdx.x] = t[threadIdx.x][i];
}

// ---------------------------------------------------------------------------
// mma.sync bf16 split GEMM (validated R4). 128x128 tile, KC=32, 8 warps.
// ---------------------------------------------------------------------------
#define PLANE_OFS 10240u
#define GEMM_DYNSMEM (2*40960)

template<int MODE>
__global__ __launch_bounds__(256, 1) void mma_gemm(
    const float* __restrict__ Ain, const float* __restrict__ bias,
    float* __restrict__ C)
{
    extern __shared__ char sm[];
    const float* A  = (MODE == 1) ? (const float*)g_att : Ain;
    const float* Bt = (MODE == 1) ? (const float*)g_woutT : (const float*)g_wqkvT;
    const int K = 1024;

    const int tid  = threadIdx.x;
    const int lane = tid & 31, wid = tid >> 5;
    const int warp_m = (wid >> 2) * 64;
    const int warp_n = (wid & 3) * 32;
    const int row0 = blockIdx.y * 128;
    const int col0 = blockIdx.x * 128;

    const uint32_t smb = smem_u32(sm);

    const int lrow  = tid >> 1;
    const int lhalf = tid & 1;
    const float* gA = A  + (size_t)(row0 + lrow) * K + lhalf * 16;
    const float* gB = Bt + (size_t)(col0 + lrow) * K + lhalf * 16;
    const uint32_t stA = (uint32_t)(lrow * 80 + lhalf * 32);
    const uint32_t stB = stA + 20480u;

    const uint32_t lm_row = (uint32_t)(lane & 15);
    const uint32_t lm_col = (lane & 16) ? 16u : 0u;
    const uint32_t aofs = (uint32_t)(warp_m + lm_row) * 80 + lm_col;
    const uint32_t bofs = 20480u + (uint32_t)(warp_n + lm_row) * 80 + lm_col;

    float acc[4][4][4];
    #pragma unroll
    for (int t = 0; t < 4; t++)
        #pragma unroll
        for (int j = 0; j < 4; j++)
            #pragma unroll
            for (int r = 0; r < 4; r++) acc[t][j][r] = 0.f;

    float4 stg[8];
    #pragma unroll
    for (int i = 0; i < 4; i++) stg[i]     = *(const float4*)(gA + i * 4);
    #pragma unroll
    for (int i = 0; i < 4; i++) stg[4 + i] = *(const float4*)(gB + i * 4);
    cvt_sts16p(&stg[0], smb + stA, PLANE_OFS);
    cvt_sts16p(&stg[4], smb + stB, PLANE_OFS);
    __syncthreads();

    for (int c = 0; c < 32; ++c) {
        const uint32_t buf = smb + (uint32_t)(c & 1) * 40960u;
        if (c < 31) {
            const float* pA = gA + (c + 1) * 32;
            const float* pB = gB + (c + 1) * 32;
            #pragma unroll
            for (int i = 0; i < 4; i++) stg[i]     = *(const float4*)(pA + i * 4);
            #pragma unroll
            for (int i = 0; i < 4; i++) stg[4 + i] = *(const float4*)(pB + i * 4);
        }
        #pragma unroll
        for (int ks = 0; ks < 2; ++ks) {
            uint32_t Ah[4][4], Am[4][4], Bh[2][4], Bm[2][4];
            #pragma unroll
            for (int t = 0; t < 4; t++) {
                uint32_t ad = buf + aofs + (uint32_t)(t * 16 * 80 + ks * 32);
                ldsm4(Ah[t], ad);
                ldsm4(Am[t], ad + PLANE_OFS);
            }
            #pragma unroll
            for (int u = 0; u < 2; u++) {
                uint32_t bd = buf + bofs + (uint32_t)(u * 16 * 80 + ks * 32);
                ldsm4(Bh[u], bd);
                ldsm4(Bm[u], bd + PLANE_OFS);
            }
            #pragma unroll
            for (int t = 0; t < 4; t++)
                #pragma unroll
                for (int j = 0; j < 4; j++) {
                    const int u = j >> 1, s = j & 1;
                    mma_bf16(acc[t][j], Ah[t], Bh[u][s], Bh[u][s + 2]);
                    mma_bf16(acc[t][j], Ah[t], Bm[u][s], Bm[u][s + 2]);
                    mma_bf16(acc[t][j], Am[t], Bh[u][s], Bh[u][s + 2]);
                }
        }
        if (c < 31) {
            const uint32_t nb = smb + (uint32_t)((c + 1) & 1) * 40960u;
            cvt_sts16p(&stg[0], nb + stA, PLANE_OFS);
            cvt_sts16p(&stg[4], nb + stB, PLANE_OFS);
        }
        __syncthreads();
    }

    const int g  = lane >> 2;
    const int tg = lane & 3;
    #pragma unroll
    for (int t = 0; t < 4; t++) {
        const int rowA = row0 + warp_m + t * 16 + g;
        #pragma unroll
        for (int j = 0; j < 4; j++) {
            const int cg = col0 + warp_n + j * 8 + 2 * tg;
            float2 lo = make_float2(acc[t][j][0], acc[t][j][1]);
            float2 hi = make_float2(acc[t][j][2], acc[t][j][3]);
            if (MODE == 0) {
                const int part = cg >> 10;
                const int w = cg & 1023;
                const int h = w >> 6, d = w & 63;
                #pragma unroll
                for (int rr = 0; rr < 2; rr++) {
                    const int row = rowA + rr * 8;
                    const int b = row >> 11, n = row & (SEQ - 1);
                    const size_t idx = ((size_t)((b * HEADS + h) * SEQ + n)) * DHEAD + d;
                    float2 v = rr ? hi : lo;
                    if (part == 0) {
                        v.x *= QSCALE; v.y *= QSCALE;
                        *(float2*)(g_q + idx) = v;
                    } else if (part == 1) {
                        *(float2*)(g_k + idx) = v;
                    } else {
                        *(float2*)(g_v + idx) = v;
                    }
                }
            } else {
                const float bx = bias[cg], by = bias[cg + 1];
                lo.x += bx; lo.y += by;
                hi.x += bx; hi.y += by;
                *(float2*)(C + (size_t)rowA * DIM + cg) = lo;
                *(float2*)(C + (size_t)(rowA + 8) * DIM + cg) = hi;
            }
        }
    }
}

// ---------------------------------------------------------------------------
// Tensor-core flash attention. CTA = 128 Q rows x one (b,h); 8 warps x 16 rows.
// KV chunks of 64, double-buffered bf16 hi/mid smem planes (pitch 144 = 9x16,
// conflict-free ldmatrix). S: A=Q regs, B=K (validated GEMM mapping).
// Softmax in accumulator registers (base-2; log2e folded into Q).
// PV: A=P repacked from S accumulators (hi+mid), B=V via ldmatrix.trans.
// Per-buffer planes: Kh@0 Km@9216 Vh@18432 Vm@27648 (stride 36864).
// ---------------------------------------------------------------------------
#define ATT_PITCH 144
#define ATT_PLANE 9216u
#define ATT_BUF   36864u
#define ATT_SMEM  (2*36864)

__global__ __launch_bounds__(256, 1) void attn_mma_kernel()
{
    extern __shared__ char sm[];
    const uint32_t smb = smem_u32(sm);
    const int tid  = threadIdx.x;
    const int lane = tid & 31, wid = tid >> 5;
    const int bh = blockIdx.y;
    const int q0 = blockIdx.x * 128;
    const int warp_m = wid * 16;

    const float* Qp = g_q + ((size_t)bh * SEQ + q0) * DHEAD;
    const float* Kp = g_k + (size_t)bh * SEQ * DHEAD;
    const float* Vp = g_v + (size_t)bh * SEQ * DHEAD;

    const int g  = lane >> 2, tg = lane & 3;
    const uint32_t lm_row  = (uint32_t)(lane & 15);
    const uint32_t lm_half = (lane & 16) ? 16u : 0u;
    const uint32_t lterm   = lm_row * ATT_PITCH + lm_half;

    // Q fragments (hi+mid) loaded once, directly from global.
    // a0=(g,2tg) a1=(g+8,2tg) a2=(g,2tg+8) a3=(g+8,2tg+8), k-step ks*16.
    uint32_t qh[4][4], qm[4][4];
    {
        const float* qb = Qp + (size_t)(warp_m + g) * DHEAD;
        #pragma unroll
        for (int ks = 0; ks < 4; ks++) {
            float2 v;
            v = *(const float2*)(qb + ks*16 + 2*tg);               cvt2(v.x, v.y, qh[ks][0], qm[ks][0]);
            v = *(const float2*)(qb + 8*DHEAD + ks*16 + 2*tg);     cvt2(v.x, v.y, qh[ks][1], qm[ks][1]);
            v = *(const float2*)(qb + ks*16 + 8 + 2*tg);           cvt2(v.x, v.y, qh[ks][2], qm[ks][2]);
            v = *(const float2*)(qb + 8*DHEAD + ks*16 + 8 + 2*tg); cvt2(v.x, v.y, qh[ks][3], qm[ks][3]);
        }
    }

    // KV loader mapping: thread -> (kv row, 16-float quarter)
    const int lkv = tid >> 2;
    const int ld0 = (tid & 3) * 16;
    const float* gK = Kp + (size_t)lkv * DHEAD + ld0;
    const float* gV = Vp + (size_t)lkv * DHEAD + ld0;
    const uint32_t stofs = (uint32_t)(lkv * ATT_PITCH + ld0 * 2);

    float4 stK[4], stV[4];
    #pragma unroll
    for (int i = 0; i < 4; i++) { stK[i] = *(const float4*)(gK + i*4); stV[i] = *(const float4*)(gV + i*4); }
    cvt_sts16p(stK, smb + stofs, ATT_PLANE);
    cvt_sts16p(stV, smb + stofs + 18432u, ATT_PLANE);
    __syncthreads();

    float m0 = -1e30f, m1 = -1e30f, l0 = 0.f, l1 = 0.f;
    float o[8][4];
    #pragma unroll
    for (int u = 0; u < 8; u++)
        #pragma unroll
        for (int r = 0; r < 4; r++) o[u][r] = 0.f;

    for (int c = 0; c < 32; ++c) {
        const uint32_t buf = smb + (uint32_t)(c & 1) * ATT_BUF;
        if (c < 31) {
            const float* pK = gK + (size_t)(c + 1) * 64 * DHEAD;
            const float* pV = gV + (size_t)(c + 1) * 64 * DHEAD;
            #pragma unroll
            for (int i = 0; i < 4; i++) { stK[i] = *(const float4*)(pK + i*4); stV[i] = *(const float4*)(pV + i*4); }
        }

        // ---- S = Q @ K^T (3-pass bf16 split) ----
        float s[8][4];
        #pragma unroll
        for (int j = 0; j < 8; j++)
            #pragma unroll
            for (int r = 0; r < 4; r++) s[j][r] = 0.f;

        #pragma unroll
        for (int ks = 0; ks < 4; ks++) {
            #pragma unroll
            for (int u = 0; u < 4; u++) {
                uint32_t bh4[4], bm4[4];
                const uint32_t ka = buf + (uint32_t)(u * 16 * ATT_PITCH) + lterm + (uint32_t)(ks * 32);
                ldsm4(bh4, ka);
                ldsm4(bm4, ka + ATT_PLANE);
                #pragma unroll
                for (int ss = 0; ss < 2; ss++) {
                    const int j = 2*u + ss;
                    mma_bf16(s[j], qh[ks], bh4[ss], bh4[ss + 2]);
                    mma_bf16(s[j], qh[ks], bm4[ss], bm4[ss + 2]);
                    mma_bf16(s[j], qm[ks], bh4[ss], bh4[ss + 2]);
                }
            }
        }

        // ---- online softmax (rows g and g+8; cols spread over tg lanes) ----
        float mlo = s[0][0], mhi = s[0][2];
        #pragma unroll
        for (int j = 0; j < 8; j++) {
            mlo = fmaxf(mlo, fmaxf(s[j][0], s[j][1]));
            mhi = fmaxf(mhi, fmaxf(s[j][2], s[j][3]));
        }
        mlo = fmaxf(mlo, __shfl_xor_sync(0xffffffffu, mlo, 1));
        mlo = fmaxf(mlo, __shfl_xor_sync(0xffffffffu, mlo, 2));
        mhi = fmaxf(mhi, __shfl_xor_sync(0xffffffffu, mhi, 1));
        mhi = fmaxf(mhi, __shfl_xor_sync(0xffffffffu, mhi, 2));
        const float mn0 = fmaxf(m0, mlo), mn1 = fmaxf(m1, mhi);
        const float al0 = ex2(m0 - mn0),  al1 = ex2(m1 - mn1);
        m0 = mn0; m1 = mn1;

        float sum0 = 0.f, sum1 = 0.f;
        #pragma unroll
        for (int j = 0; j < 8; j++) {
            s[j][0] = ex2(s[j][0] - mn0); sum0 += s[j][0];
            s[j][1] = ex2(s[j][1] - mn0); sum0 += s[j][1];
            s[j][2] = ex2(s[j][2] - mn1); sum1 += s[j][2];
            s[j][3] = ex2(s[j][3] - mn1); sum1 += s[j][3];
        }
        sum0 += __shfl_xor_sync(0xffffffffu, sum0, 1);
        sum0 += __shfl_xor_sync(0xffffffffu, sum0, 2);
        sum1 += __shfl_xor_sync(0xffffffffu, sum1, 1);
        sum1 += __shfl_xor_sync(0xffffffffu, sum1, 2);
        l0 = l0 * al0 + sum0;
        l1 = l1 * al1 + sum1;

        #pragma unroll
        for (int u = 0; u < 8; u++) {
            o[u][0] *= al0; o[u][1] *= al0;
            o[u][2] *= al1; o[u][3] *= al1;
        }

        // ---- O += P @ V (P from S regs, hi+mid; V via ldmatrix.trans) ----
        #pragma unroll
        for (int kk = 0; kk < 4; kk++) {
            uint32_t pah[4], pam[4];
            cvt2(s[2*kk][0],   s[2*kk][1],   pah[0], pam[0]);
            cvt2(s[2*kk][2],   s[2*kk][3],   pah[1], pam[1]);
            cvt2(s[2*kk+1][0], s[2*kk+1][1], pah[2], pam[2]);
            cvt2(s[2*kk+1][2], s[2*kk+1][3], pah[3], pam[3]);
            #pragma unroll
            for (int u = 0; u < 4; u++) {
                uint32_t vh[4], vm[4];
                const uint32_t va = buf + 18432u + (uint32_t)(kk * 16 * ATT_PITCH)
                                  + lm_row * ATT_PITCH + (uint32_t)(u * 32) + lm_half;
                ldsm4t(vh, va);
                ldsm4t(vm, va + ATT_PLANE);
                mma_bf16(o[2*u],   pah, vh[0], vh[1]);
                mma_bf16(o[2*u],   pah, vm[0], vm[1]);
                mma_bf16(o[2*u],   pam, vh[0], vh[1]);
                mma_bf16(o[2*u+1], pah, vh[2], vh[3]);
                mma_bf16(o[2*u+1], pah, vm[2], vm[3]);
                mma_bf16(o[2*u+1], pam, vh[2], vh[3]);
            }
        }

        if (c < 31) {
            const uint32_t nb = smb + (uint32_t)((c + 1) & 1) * ATT_BUF;
            cvt_sts16p(stK, nb + stofs, ATT_PLANE);
            cvt_sts16p(stV, nb + stofs + 18432u, ATT_PLANE);
        }
        __syncthreads();
    }

    // ---- epilogue: O / l -> g_att [b*n, h*64] ----
    const float inv0 = 1.f / l0, inv1 = 1.f / l1;
    const int b = bh >> 4, h = bh & 15;
    const int row_lo = q0 + warp_m + g;
    float* dst0 = g_att + ((size_t)(b * SEQ + row_lo)) * DIM + h * DHEAD;
    float* dst1 = dst0 + (size_t)8 * DIM;
    #pragma unroll
    for (int u = 0; u < 8; u++) {
        const int cg = u * 8 + 2 * tg;
        *(float2*)(dst0 + cg) = make_float2(o[u][0] * inv0, o[u][1] * inv0);
        *(float2*)(dst1 + cg) = make_float2(o[u][2] * inv1, o[u][3] * inv1);
    }
}

// ---------------------------------------------------------------------------
extern "C" void kernel_launch(void* const* d_in, const int* in_sizes, int n_in,
                              void* d_out, int out_size)
{
    const float* x     = (const float*)d_in[0];
    const float* w_qkv = (const float*)d_in[1];
    const float* w_out = (const float*)d_in[2];
    const float* b_out = (const float*)d_in[3];
    float* out = (float*)d_out;
    (void)in_sizes; (void)n_in; (void)out_size;

    cudaFuncSetAttribute(mma_gemm<0>, cudaFuncAttributeMaxDynamicSharedMemorySize, GEMM_DYNSMEM);
    cudaFuncSetAttribute(mma_gemm<1>, cudaFuncAttributeMaxDynamicSharedMemorySize, GEMM_DYNSMEM);
    cudaFuncSetAttribute(attn_mma_kernel, cudaFuncAttributeMaxDynamicSharedMemorySize, ATT_SMEM);

    // Transpose weights (K-major operands)
    transpose_kernel<DIM, QKVN, 0><<<dim3(QKVN / 32, DIM / 32), dim3(32, 8)>>>(w_qkv);
    transpose_kernel<DIM, DIM, 1><<<dim3(DIM / 32, DIM / 32), dim3(32, 8)>>>(w_out);

    // QKV projection (mma.sync bf16-split); Q pre-scaled by DIM^-0.5 * log2e
    dim3 gq(QKVN / 128, MTOT / 128);
    mma_gemm<0><<<gq, 256, GEMM_DYNSMEM>>>(x, nullptr, nullptr);

    // Tensor-core flash attention
    dim3 ga(SEQ / 128, BATCH * HEADS);
    attn_mma_kernel<<<ga, 256, ATT_SMEM>>>();

    // Output projection (mma.sync bf16-split) + bias
    dim3 go(DIM / 128, MTOT / 128);
    mma_gemm<1><<<go, 256, GEMM_DYNSMEM>>>(nullptr, b_out, out);
}

// round 6
// speedup vs baseline: 3.5242x; 1.0033x over previous
#include <cuda_runtime.h>
#include <cuda_bf16.h>
#include <cstdint>
#include <math.h>

#define BATCH 4
#define HEADS 16
#define SEQ   2048
#define DIM   1024
#define DHEAD 64
#define LOG2E 1.4426950408889634f
#define QSCALE (0.03125f * LOG2E)     // DIM^-0.5 * log2(e), folded into Q

#define MTOT  (BATCH*SEQ)         // 8192
#define QKVN  (3*HEADS*DHEAD)     // 3072
#define QKVELEM (BATCH*HEADS*SEQ*DHEAD)

// Scratch (device globals). bf16 "hi/mid" plane pairs represent fp32 to ~16
// mantissa bits; converted ONCE at producer, consumed raw by mma loaders.
__device__ float          g_q  [QKVELEM];        // fp32, pre-scaled by QSCALE
__device__ __nv_bfloat16  g_kh [QKVELEM], g_km [QKVELEM];   // [b,h,n,d]
__device__ __nv_bfloat16  g_vh [QKVELEM], g_vm [QKVELEM];
__device__ __nv_bfloat16  g_atth[MTOT*DIM], g_attm[MTOT*DIM];   // [b*n, h*d]
__device__ __nv_bfloat16  g_xh [MTOT*DIM], g_xm [MTOT*DIM];
__device__ __nv_bfloat16  g_wqkvTh[QKVN*DIM], g_wqkvTm[QKVN*DIM];
__device__ __nv_bfloat16  g_woutTh[DIM*DIM],  g_woutTm[DIM*DIM];

// ---------------------------------------------------------------------------
// Helpers
// ---------------------------------------------------------------------------
__device__ __forceinline__ uint32_t smem_u32(const void* p) {
    uint32_t a;
    asm("{ .reg .u64 t; cvta.to.shared.u64 t, %1; cvt.u32.u64 %0, t; }"
        : "=r"(a) : "l"(p));
    return a;
}
__device__ __forceinline__ void ldsm4(uint32_t* r, uint32_t addr) {
    asm volatile("ldmatrix.sync.aligned.m8n8.x4.shared.b16 {%0,%1,%2,%3}, [%4];"
                 : "=r"(r[0]), "=r"(r[1]), "=r"(r[2]), "=r"(r[3]) : "r"(addr));
}
__device__ __forceinline__ void ldsm4t(uint32_t* r, uint32_t addr) {
    asm volatile("ldmatrix.sync.aligned.m8n8.x4.trans.shared.b16 {%0,%1,%2,%3}, [%4];"
                 : "=r"(r[0]), "=r"(r[1]), "=r"(r[2]), "=r"(r[3]) : "r"(addr));
}
__device__ __forceinline__ void mma_bf16(float* c, const uint32_t* a,
                                         uint32_t b0, uint32_t b1) {
    asm volatile("mma.sync.aligned.m16n8k16.row.col.f32.bf16.bf16.f32 "
                 "{%0,%1,%2,%3}, {%4,%5,%6,%7}, {%8,%9}, {%0,%1,%2,%3};"
                 : "+f"(c[0]), "+f"(c[1]), "+f"(c[2]), "+f"(c[3])
                 : "r"(a[0]), "r"(a[1]), "r"(a[2]), "r"(a[3]),
                   "r"(b0), "r"(b1));
}
__device__ __forceinline__ void sts128u(uint32_t addr, const uint32_t* v) {
    asm volatile("st.shared.v4.b32 [%0], {%1,%2,%3,%4};"
                 :: "r"(addr), "r"(v[0]), "r"(v[1]), "r"(v[2]), "r"(v[3]) : "memory");
}
__device__ __forceinline__ float ex2(float x) {
    float y;
    asm("ex2.approx.ftz.f32 %0, %1;" : "=f"(y) : "f"(x));
    return y;
}
__device__ __forceinline__ void cvt2(float x, float y, uint32_t& h, uint32_t& m) {
    __nv_bfloat162 hh = __floats2bfloat162_rn(x, y);
    float rx = x - __bfloat162float(hh.x);
    float ry = y - __bfloat162float(hh.y);
    __nv_bfloat162 mm = __floats2bfloat162_rn(rx, ry);
    h = *(const uint32_t*)&hh;
    m = *(const uint32_t*)&mm;
}

// ---------------------------------------------------------------------------
// One-time producers: x -> planes; w^T -> planes
// ---------------------------------------------------------------------------
__global__ __launch_bounds__(256) void cvt_x_kernel(const float* __restrict__ x)
{
    const size_t i = (size_t)blockIdx.x * 256 + threadIdx.x;   // float4 index
    float4 v = ((const float4*)x)[i];
    uint32_t h0, m0, h1, m1;
    cvt2(v.x, v.y, h0, m0);
    cvt2(v.z, v.w, h1, m1);
    ((uint2*)g_xh)[i] = make_uint2(h0, h1);
    ((uint2*)g_xm)[i] = make_uint2(m0, m1);
}

template<int R, int C, int WHICH>
__global__ __launch_bounds__(256) void transpose_kernel(const float* __restrict__ src)
{
    __shared__ float t[32][33];
    __nv_bfloat16* dh = WHICH ? g_woutTh : g_wqkvTh;
    __nv_bfloat16* dm = WHICH ? g_woutTm : g_wqkvTm;
    int c0 = blockIdx.x * 32, r0 = blockIdx.y * 32;
    #pragma unroll
    for (int i = threadIdx.y; i < 32; i += 8)
        t[i][threadIdx.x] = src[(size_t)(r0 + i) * C + c0 + threadIdx.x];
    __syncthreads();
    #pragma unroll
    for (int i = threadIdx.y; i < 32; i += 8) {
        float v = t[threadIdx.x][i];
        __nv_bfloat16 hh = __float2bfloat16(v);
        __nv_bfloat16 mm = __float2bfloat16(v - __bfloat162float(hh));
        size_t idx = (size_t)(c0 + i) * R + r0 + threadIdx.x;
        dh[idx] = hh;
        dm[idx] = mm;
    }
}

// ---------------------------------------------------------------------------
// mma.sync bf16 split GEMM over preconverted planes. 128x128 tile, KC=32,
// 8 warps (64x32 each). Smem per buffer (pitch 80B, conflict-free ldsm):
//   A_hi @0, A_mid @10240, B_hi @20480, B_mid @30720  (40960 B/buffer)
// MODE 0: x @ w_qkv -> g_q(*QSCALE) fp32 + K/V bf16 planes.
// MODE 1: att @ w_out + bias -> out fp32.
// ---------------------------------------------------------------------------
#define PLANE_OFS 10240u
#define GEMM_DYNSMEM (2*40960)

template<int MODE>
__global__ __launch_bounds__(256, 1) void mma_gemm(
    const float* __restrict__ bias, float* __restrict__ C)
{
    extern __shared__ char sm[];
    const uint32_t* Ah = (const uint32_t*)(MODE ? g_atth : g_xh);
    const uint32_t* Am = (const uint32_t*)(MODE ? g_attm : g_xm);
    const uint32_t* Bh = (const uint32_t*)(MODE ? g_woutTh : g_wqkvTh);
    const uint32_t* Bm = (const uint32_t*)(MODE ? g_woutTm : g_wqkvTm);
    const int K = 1024;

    const int tid  = threadIdx.x;
    const int lane = tid & 31, wid = tid >> 5;
    const int warp_m = (wid >> 2) * 64;
    const int warp_n = (wid & 3) * 32;
    const int row0 = blockIdx.y * 128;
    const int col0 = blockIdx.x * 128;

    const uint32_t smb = smem_u32(sm);

    // Loader: thread -> (row, 16-elem k-half). Pair (2 elem = 1 u32) indexing.
    const int lrow  = tid >> 1;
    const int lhalf = tid & 1;
    const uint32_t* pAh = Ah + ((size_t)(row0 + lrow) * K >> 1) + lhalf * 8;
    const uint32_t* pAm = Am + ((size_t)(row0 + lrow) * K >> 1) + lhalf * 8;
    const uint32_t* pBh = Bh + ((size_t)(col0 + lrow) * K >> 1) + lhalf * 8;
    const uint32_t* pBm = Bm + ((size_t)(col0 + lrow) * K >> 1) + lhalf * 8;
    const uint32_t stA = (uint32_t)(lrow * 80 + lhalf * 32);
    const uint32_t stB = stA + 20480u;

    const uint32_t lm_row = (uint32_t)(lane & 15);
    const uint32_t lm_col = (lane & 16) ? 16u : 0u;
    const uint32_t aofs = (uint32_t)(warp_m + lm_row) * 80 + lm_col;
    const uint32_t bofs = 20480u + (uint32_t)(warp_n + lm_row) * 80 + lm_col;

    float acc[4][4][4];
    #pragma unroll
    for (int t = 0; t < 4; t++)
        #pragma unroll
        for (int j = 0; j < 4; j++)
            #pragma unroll
            for (int r = 0; r < 4; r++) acc[t][j][r] = 0.f;

    uint4 stg[8];   // Ah0 Ah1 Am0 Am1 Bh0 Bh1 Bm0 Bm1
    stg[0] = *(const uint4*)(pAh);     stg[1] = *(const uint4*)(pAh + 4);
    stg[2] = *(const uint4*)(pAm);     stg[3] = *(const uint4*)(pAm + 4);
    stg[4] = *(const uint4*)(pBh);     stg[5] = *(const uint4*)(pBh + 4);
    stg[6] = *(const uint4*)(pBm);     stg[7] = *(const uint4*)(pBm + 4);
    {
        const uint32_t b0 = smb;
        sts128u(b0 + stA,              (const uint32_t*)&stg[0]);
        sts128u(b0 + stA + 16,         (const uint32_t*)&stg[1]);
        sts128u(b0 + stA + PLANE_OFS,      (const uint32_t*)&stg[2]);
        sts128u(b0 + stA + PLANE_OFS + 16, (const uint32_t*)&stg[3]);
        sts128u(b0 + stB,              (const uint32_t*)&stg[4]);
        sts128u(b0 + stB + 16,         (const uint32_t*)&stg[5]);
        sts128u(b0 + stB + PLANE_OFS,      (const uint32_t*)&stg[6]);
        sts128u(b0 + stB + PLANE_OFS + 16, (const uint32_t*)&stg[7]);
    }
    __syncthreads();

    for (int c = 0; c < 32; ++c) {
        const uint32_t buf = smb + (uint32_t)(c & 1) * 40960u;
        if (c < 31) {
            const int o = (c + 1) * 16;   // 16 pairs per 32-elem chunk
            stg[0] = *(const uint4*)(pAh + o);     stg[1] = *(const uint4*)(pAh + o + 4);
            stg[2] = *(const uint4*)(pAm + o);     stg[3] = *(const uint4*)(pAm + o + 4);
            stg[4] = *(const uint4*)(pBh + o);     stg[5] = *(const uint4*)(pBh + o + 4);
            stg[6] = *(const uint4*)(pBm + o);     stg[7] = *(const uint4*)(pBm + o + 4);
        }
        #pragma unroll
        for (int ks = 0; ks < 2; ++ks) {
            uint32_t Af[4][4], Amf[4][4], Bf[2][4], Bmf[2][4];
            #pragma unroll
            for (int t = 0; t < 4; t++) {
                uint32_t ad = buf + aofs + (uint32_t)(t * 16 * 80 + ks * 32);
                ldsm4(Af[t], ad);
                ldsm4(Amf[t], ad + PLANE_OFS);
            }
            #pragma unroll
            for (int u = 0; u < 2; u++) {
                uint32_t bd = buf + bofs + (uint32_t)(u * 16 * 80 + ks * 32);
                ldsm4(Bf[u], bd);
                ldsm4(Bmf[u], bd + PLANE_OFS);
            }
            #pragma unroll
            for (int t = 0; t < 4; t++)
                #pragma unroll
                for (int j = 0; j < 4; j++) {
                    const int u = j >> 1, s = j & 1;
                    mma_bf16(acc[t][j], Af[t],  Bf[u][s],  Bf[u][s + 2]);
                    mma_bf16(acc[t][j], Af[t],  Bmf[u][s], Bmf[u][s + 2]);
                    mma_bf16(acc[t][j], Amf[t], Bf[u][s],  Bf[u][s + 2]);
                }
        }
        if (c < 31) {
            const uint32_t nb = smb + (uint32_t)((c + 1) & 1) * 40960u;
            sts128u(nb + stA,              (const uint32_t*)&stg[0]);
            sts128u(nb + stA + 16,         (const uint32_t*)&stg[1]);
            sts128u(nb + stA + PLANE_OFS,      (const uint32_t*)&stg[2]);
            sts128u(nb + stA + PLANE_OFS + 16, (const uint32_t*)&stg[3]);
            sts128u(nb + stB,              (const uint32_t*)&stg[4]);
            sts128u(nb + stB + 16,         (const uint32_t*)&stg[5]);
            sts128u(nb + stB + PLANE_OFS,      (const uint32_t*)&stg[6]);
            sts128u(nb + stB + PLANE_OFS + 16, (const uint32_t*)&stg[7]);
        }
        __syncthreads();
    }

    const int g  = lane >> 2;
    const int tg = lane & 3;
    #pragma unroll
    for (int t = 0; t < 4; t++) {
        const int rowA = row0 + warp_m + t * 16 + g;
        #pragma unroll
        for (int j = 0; j < 4; j++) {
            const int cg = col0 + warp_n + j * 8 + 2 * tg;
            float2 lo = make_float2(acc[t][j][0], acc[t][j][1]);
            float2 hi = make_float2(acc[t][j][2], acc[t][j][3]);
            if (MODE == 0) {
                const int part = cg >> 10;
                const int w = cg & 1023;
                const int h = w >> 6, d = w & 63;
                #pragma unroll
                for (int rr = 0; rr < 2; rr++) {
                    const int row = rowA + rr * 8;
                    const int b = row >> 11, n = row & (SEQ - 1);
                    const size_t idx = ((size_t)((b * HEADS + h) * SEQ + n)) * DHEAD + d;
                    float2 v = rr ? hi : lo;
                    if (part == 0) {
                        v.x *= QSCALE; v.y *= QSCALE;
                        *(float2*)(g_q + idx) = v;
                    } else {
                        uint32_t ph, pm;
                        cvt2(v.x, v.y, ph, pm);
                        if (part == 1) {
                            ((uint32_t*)g_kh)[idx >> 1] = ph;
                            ((uint32_t*)g_km)[idx >> 1] = pm;
                        } else {
                            ((uint32_t*)g_vh)[idx >> 1] = ph;
                            ((uint32_t*)g_vm)[idx >> 1] = pm;
                        }
                    }
                }
            } else {
                const float bx = bias[cg], by = bias[cg + 1];
                lo.x += bx; lo.y += by;
                hi.x += bx; hi.y += by;
                *(float2*)(C + (size_t)rowA * DIM + cg) = lo;
                *(float2*)(C + (size_t)(rowA + 8) * DIM + cg) = hi;
            }
        }
    }
}

// ---------------------------------------------------------------------------
// Tensor-core flash attention over preconverted K/V planes.
// CTA = 128 Q rows x one (b,h); 8 warps x 16 rows; KV chunks of 64;
// double-buffered smem, pitch 144 (conflict-free ldsm).
// Planes per buffer: Kh@0 Km@9216 Vh@18432 Vm@27648 (stride 36864).
// ---------------------------------------------------------------------------
#define ATT_PITCH 144
#define ATT_PLANE 9216u
#define ATT_BUF   36864u
#define ATT_SMEM  (2*36864)

__global__ __launch_bounds__(256, 1) void attn_mma_kernel()
{
    extern __shared__ char sm[];
    const uint32_t smb = smem_u32(sm);
    const int tid  = threadIdx.x;
    const int lane = tid & 31, wid = tid >> 5;
    const int bh = blockIdx.y;
    const int q0 = blockIdx.x * 128;
    const int warp_m = wid * 16;

    const float* Qp = g_q + ((size_t)bh * SEQ + q0) * DHEAD;
    const size_t kvbase = (size_t)bh * SEQ * DHEAD;

    const int g  = lane >> 2, tg = lane & 3;
    const uint32_t lm_row  = (uint32_t)(lane & 15);
    const uint32_t lm_half = (lane & 16) ? 16u : 0u;
    const uint32_t lterm   = lm_row * ATT_PITCH + lm_half;

    // Q fragments (hi+mid) from fp32, once.
    uint32_t qh[4][4], qm[4][4];
    {
        const float* qb = Qp + (size_t)(warp_m + g) * DHEAD;
        #pragma unroll
        for (int ks = 0; ks < 4; ks++) {
            float2 v;
            v = *(const float2*)(qb + ks*16 + 2*tg);               cvt2(v.x, v.y, qh[ks][0], qm[ks][0]);
            v = *(const float2*)(qb + 8*DHEAD + ks*16 + 2*tg);     cvt2(v.x, v.y, qh[ks][1], qm[ks][1]);
            v = *(const float2*)(qb + ks*16 + 8 + 2*tg);           cvt2(v.x, v.y, qh[ks][2], qm[ks][2]);
            v = *(const float2*)(qb + 8*DHEAD + ks*16 + 8 + 2*tg); cvt2(v.x, v.y, qh[ks][3], qm[ks][3]);
        }
    }

    // KV loader: thread -> (kv row, 16-elem quarter); pair indexing.
    const int lkv = tid >> 2;
    const int ld0 = (tid & 3) * 16;
    const size_t pbase = (kvbase + (size_t)lkv * DHEAD + ld0) >> 1;
    const uint32_t* pKh = (const uint32_t*)g_kh + pbase;
    const uint32_t* pKm = (const uint32_t*)g_km + pbase;
    const uint32_t* pVh = (const uint32_t*)g_vh + pbase;
    const uint32_t* pVm = (const uint32_t*)g_vm + pbase;
    const uint32_t stofs = (uint32_t)(lkv * ATT_PITCH + ld0 * 2);

    uint4 stg[8];   // Kh0 Kh1 Km0 Km1 Vh0 Vh1 Vm0 Vm1
    stg[0] = *(const uint4*)(pKh); stg[1] = *(const uint4*)(pKh + 4);
    stg[2] = *(const uint4*)(pKm); stg[3] = *(const uint4*)(pKm + 4);
    stg[4] = *(const uint4*)(pVh); stg[5] = *(const uint4*)(pVh + 4);
    stg[6] = *(const uint4*)(pVm); stg[7] = *(const uint4*)(pVm + 4);
    {
        sts128u(smb + stofs,                   (const uint32_t*)&stg[0]);
        sts128u(smb + stofs + 16,              (const uint32_t*)&stg[1]);
        sts128u(smb + stofs + ATT_PLANE,       (const uint32_t*)&stg[2]);
        sts128u(smb + stofs + ATT_PLANE + 16,  (const uint32_t*)&stg[3]);
        sts128u(smb + stofs + 18432u,              (const uint32_t*)&stg[4]);
        sts128u(smb + stofs + 18432u + 16,         (const uint32_t*)&stg[5]);
        sts128u(smb + stofs + 18432u + ATT_PLANE,      (const uint32_t*)&stg[6]);
        sts128u(smb + stofs + 18432u + ATT_PLANE + 16, (const uint32_t*)&stg[7]);
    }
    __syncthreads();

    float m0 = -1e30f, m1 = -1e30f, l0 = 0.f, l1 = 0.f;
    float o[8][4];
    #pragma unroll
    for (int u = 0; u < 8; u++)
        #pragma unroll
        for (int r = 0; r < 4; r++) o[u][r] = 0.f;

    for (int c = 0; c < 32; ++c) {
        const uint32_t buf = smb + (uint32_t)(c & 1) * ATT_BUF;
        if (c < 31) {
            const int o4 = (c + 1) * 64 * DHEAD / 2;     // pairs per chunk
            stg[0] = *(const uint4*)(pKh + o4); stg[1] = *(const uint4*)(pKh + o4 + 4);
            stg[2] = *(const uint4*)(pKm + o4); stg[3] = *(const uint4*)(pKm + o4 + 4);
            stg[4] = *(const uint4*)(pVh + o4); stg[5] = *(const uint4*)(pVh + o4 + 4);
            stg[6] = *(const uint4*)(pVm + o4); stg[7] = *(const uint4*)(pVm + o4 + 4);
        }

        // ---- S = Q @ K^T ----
        float s[8][4];
        #pragma unroll
        for (int j = 0; j < 8; j++)
            #pragma unroll
            for (int r = 0; r < 4; r++) s[j][r] = 0.f;

        #pragma unroll
        for (int ks = 0; ks < 4; ks++) {
            #pragma unroll
            for (int u = 0; u < 4; u++) {
                uint32_t bh4[4], bm4[4];
                const uint32_t ka = buf + (uint32_t)(u * 16 * ATT_PITCH) + lterm + (uint32_t)(ks * 32);
                ldsm4(bh4, ka);
                ldsm4(bm4, ka + ATT_PLANE);
                #pragma unroll
                for (int ss = 0; ss < 2; ss++) {
                    const int j = 2*u + ss;
                    mma_bf16(s[j], qh[ks], bh4[ss], bh4[ss + 2]);
                    mma_bf16(s[j], qh[ks], bm4[ss], bm4[ss + 2]);
                    mma_bf16(s[j], qm[ks], bh4[ss], bh4[ss + 2]);
                }
            }
        }

        // ---- online softmax (base-2) ----
        float mlo = s[0][0], mhi = s[0][2];
        #pragma unroll
        for (int j = 0; j < 8; j++) {
            mlo = fmaxf(mlo, fmaxf(s[j][0], s[j][1]));
            mhi = fmaxf(mhi, fmaxf(s[j][2], s[j][3]));
        }
        mlo = fmaxf(mlo, __shfl_xor_sync(0xffffffffu, mlo, 1));
        mlo = fmaxf(mlo, __shfl_xor_sync(0xffffffffu, mlo, 2));
        mhi = fmaxf(mhi, __shfl_xor_sync(0xffffffffu, mhi, 1));
        mhi = fmaxf(mhi, __shfl_xor_sync(0xffffffffu, mhi, 2));
        const float mn0 = fmaxf(m0, mlo), mn1 = fmaxf(m1, mhi);
        const float al0 = ex2(m0 - mn0),  al1 = ex2(m1 - mn1);
        m0 = mn0; m1 = mn1;

        float sum0 = 0.f, sum1 = 0.f;
        #pragma unroll
        for (int j = 0; j < 8; j++) {
            s[j][0] = ex2(s[j][0] - mn0); sum0 += s[j][0];
            s[j][1] = ex2(s[j][1] - mn0); sum0 += s[j][1];
            s[j][2] = ex2(s[j][2] - mn1); sum1 += s[j][2];
            s[j][3] = ex2(s[j][3] - mn1); sum1 += s[j][3];
        }
        sum0 += __shfl_xor_sync(0xffffffffu, sum0, 1);
        sum0 += __shfl_xor_sync(0xffffffffu, sum0, 2);
        sum1 += __shfl_xor_sync(0xffffffffu, sum1, 1);
        sum1 += __shfl_xor_sync(0xffffffffu, sum1, 2);
        l0 = l0 * al0 + sum0;
        l1 = l1 * al1 + sum1;

        #pragma unroll
        for (int u = 0; u < 8; u++) {
            o[u][0] *= al0; o[u][1] *= al0;
            o[u][2] *= al1; o[u][3] *= al1;
        }

        // ---- O += P @ V ----
        #pragma unroll
        for (int kk = 0; kk < 4; kk++) {
            uint32_t pah[4], pam[4];
            cvt2(s[2*kk][0],   s[2*kk][1],   pah[0], pam[0]);
            cvt2(s[2*kk][2],   s[2*kk][3],   pah[1], pam[1]);
            cvt2(s[2*kk+1][0], s[2*kk+1][1], pah[2], pam[2]);
            cvt2(s[2*kk+1][2], s[2*kk+1][3], pah[3], pam[3]);
            #pragma unroll
            for (int u = 0; u < 4; u++) {
                uint32_t vh[4], vm[4];
                const uint32_t va = buf + 18432u + (uint32_t)(kk * 16 * ATT_PITCH)
                                  + lm_row * ATT_PITCH + (uint32_t)(u * 32) + lm_half;
                ldsm4t(vh, va);
                ldsm4t(vm, va + ATT_PLANE);
                mma_bf16(o[2*u],   pah, vh[0], vh[1]);
                mma_bf16(o[2*u],   pah, vm[0], vm[1]);
                mma_bf16(o[2*u],   pam, vh[0], vh[1]);
                mma_bf16(o[2*u+1], pah, vh[2], vh[3]);
                mma_bf16(o[2*u+1], pah, vm[2], vm[3]);
                mma_bf16(o[2*u+1], pam, vh[2], vh[3]);
            }
        }

        if (c < 31) {
            const uint32_t nb = smb + (uint32_t)((c + 1) & 1) * ATT_BUF;
            sts128u(nb + stofs,                   (const uint32_t*)&stg[0]);
            sts128u(nb + stofs + 16,              (const uint32_t*)&stg[1]);
            sts128u(nb + stofs + ATT_PLANE,       (const uint32_t*)&stg[2]);
            sts128u(nb + stofs + ATT_PLANE + 16,  (const uint32_t*)&stg[3]);
            sts128u(nb + stofs + 18432u,              (const uint32_t*)&stg[4]);
            sts128u(nb + stofs + 18432u + 16,         (const uint32_t*)&stg[5]);
            sts128u(nb + stofs + 18432u + ATT_PLANE,      (const uint32_t*)&stg[6]);
            sts128u(nb + stofs + 18432u + ATT_PLANE + 16, (const uint32_t*)&stg[7]);
        }
        __syncthreads();
    }

    // ---- epilogue: O/l -> att planes [b*n, h*64] ----
    const float inv0 = 1.f / l0, inv1 = 1.f / l1;
    const int bb = bh >> 4, hh = bh & 15;
    const int row_lo = q0 + warp_m + g;
    const size_t d0 = ((size_t)(bb * SEQ + row_lo)) * DIM + hh * DHEAD;
    const size_t d1 = d0 + (size_t)8 * DIM;
    #pragma unroll
    for (int u = 0; u < 8; u++) {
        const int cg = u * 8 + 2 * tg;
        uint32_t ph, pm;
        cvt2(o[u][0] * inv0, o[u][1] * inv0, ph, pm);
        ((uint32_t*)g_atth)[(d0 + cg) >> 1] = ph;
        ((uint32_t*)g_attm)[(d0 + cg) >> 1] = pm;
        cvt2(o[u][2] * inv1, o[u][3] * inv1, ph, pm);
        ((uint32_t*)g_atth)[(d1 + cg) >> 1] = ph;
        ((uint32_t*)g_attm)[(d1 + cg) >> 1] = pm;
    }
}

// ---------------------------------------------------------------------------
extern "C" void kernel_launch(void* const* d_in, const int* in_sizes, int n_in,
                              void* d_out, int out_size)
{
    const float* x     = (const float*)d_in[0];
    const float* w_qkv = (const float*)d_in[1];
    const float* w_out = (const float*)d_in[2];
    const float* b_out = (const float*)d_in[3];
    float* out = (float*)d_out;
    (void)in_sizes; (void)n_in; (void)out_size;

    cudaFuncSetAttribute(mma_gemm<0>, cudaFuncAttributeMaxDynamicSharedMemorySize, GEMM_DYNSMEM);
    cudaFuncSetAttribute(mma_gemm<1>, cudaFuncAttributeMaxDynamicSharedMemorySize, GEMM_DYNSMEM);
    cudaFuncSetAttribute(attn_mma_kernel, cudaFuncAttributeMaxDynamicSharedMemorySize, ATT_SMEM);

    // One-time conversions: x -> bf16 planes; weights -> transposed bf16 planes
    cvt_x_kernel<<<MTOT * DIM / 4 / 256, 256>>>(x);
    transpose_kernel<DIM, QKVN, 0><<<dim3(QKVN / 32, DIM / 32), dim3(32, 8)>>>(w_qkv);
    transpose_kernel<DIM, DIM, 1><<<dim3(DIM / 32, DIM / 32), dim3(32, 8)>>>(w_out);

    // QKV projection -> g_q (fp32, scaled) + K/V bf16 planes
    dim3 gq(QKVN / 128, MTOT / 128);
    mma_gemm<0><<<gq, 256, GEMM_DYNSMEM>>>(nullptr, nullptr);

    // Tensor-core flash attention -> att bf16 planes
    dim3 ga(SEQ / 128, BATCH * HEADS);
    attn_mma_kernel<<<ga, 256, ATT_SMEM>>>();

    // Output projection + bias -> out
    dim3 go(DIM / 128, MTOT / 128);
    mma_gemm<1><<<go, 256, GEMM_DYNSMEM>>>(b_out, out);
}

// round 7
// speedup vs baseline: 3.8375x; 1.0889x over previous
#include <cuda_runtime.h>
#include <cuda_bf16.h>
#include <cstdint>
#include <math.h>

#define BATCH 4
#define HEADS 16
#define SEQ   2048
#define DIM   1024
#define DHEAD 64
#define LOG2E 1.4426950408889634f
#define QSCALE (0.03125f * LOG2E)     // DIM^-0.5 * log2(e), folded into Q planes

#define MTOT  (BATCH*SEQ)         // 8192
#define QKVN  (3*HEADS*DHEAD)     // 3072
#define QKVELEM (BATCH*HEADS*SEQ*DHEAD)

// Scratch (device globals). bf16 hi/mid plane pairs ~= fp32 to 16 mantissa bits.
__device__ __nv_bfloat16  g_qh [QKVELEM], g_qm [QKVELEM];   // [b,h,n,d], scaled
__device__ __nv_bfloat16  g_kh [QKVELEM], g_km [QKVELEM];
__device__ __nv_bfloat16  g_vh [QKVELEM], g_vm [QKVELEM];
__device__ __nv_bfloat16  g_atth[MTOT*DIM], g_attm[MTOT*DIM];
__device__ __nv_bfloat16  g_xh [MTOT*DIM], g_xm [MTOT*DIM];
__device__ __nv_bfloat16  g_wqkvTh[QKVN*DIM], g_wqkvTm[QKVN*DIM];
__device__ __nv_bfloat16  g_woutTh[DIM*DIM],  g_woutTm[DIM*DIM];

// ---------------------------------------------------------------------------
// Helpers
// ---------------------------------------------------------------------------
__device__ __forceinline__ uint32_t smem_u32(const void* p) {
    uint32_t a;
    asm("{ .reg .u64 t; cvta.to.shared.u64 t, %1; cvt.u32.u64 %0, t; }"
        : "=r"(a) : "l"(p));
    return a;
}
__device__ __forceinline__ void ldsm4(uint32_t* r, uint32_t addr) {
    asm volatile("ldmatrix.sync.aligned.m8n8.x4.shared.b16 {%0,%1,%2,%3}, [%4];"
                 : "=r"(r[0]), "=r"(r[1]), "=r"(r[2]), "=r"(r[3]) : "r"(addr));
}
__device__ __forceinline__ void ldsm4t(uint32_t* r, uint32_t addr) {
    asm volatile("ldmatrix.sync.aligned.m8n8.x4.trans.shared.b16 {%0,%1,%2,%3}, [%4];"
                 : "=r"(r[0]), "=r"(r[1]), "=r"(r[2]), "=r"(r[3]) : "r"(addr));
}
__device__ __forceinline__ void mma_bf16(float* c, const uint32_t* a,
                                         uint32_t b0, uint32_t b1) {
    asm volatile("mma.sync.aligned.m16n8k16.row.col.f32.bf16.bf16.f32 "
                 "{%0,%1,%2,%3}, {%4,%5,%6,%7}, {%8,%9}, {%0,%1,%2,%3};"
                 : "+f"(c[0]), "+f"(c[1]), "+f"(c[2]), "+f"(c[3])
                 : "r"(a[0]), "r"(a[1]), "r"(a[2]), "r"(a[3]),
                   "r"(b0), "r"(b1));
}
__device__ __forceinline__ void cpa16(uint32_t dst, const void* src) {
    asm volatile("cp.async.cg.shared.global [%0], [%1], 16;"
                 :: "r"(dst), "l"(src) : "memory");
}
#define CPA_COMMIT() asm volatile("cp.async.commit_group;" ::: "memory")
#define CPA_WAIT0()  asm volatile("cp.async.wait_group 0;" ::: "memory")

__device__ __forceinline__ float ex2(float x) {
    float y;
    asm("ex2.approx.ftz.f32 %0, %1;" : "=f"(y) : "f"(x));
    return y;
}
__device__ __forceinline__ void cvt2(float x, float y, uint32_t& h, uint32_t& m) {
    __nv_bfloat162 hh = __floats2bfloat162_rn(x, y);
    float rx = x - __bfloat162float(hh.x);
    float ry = y - __bfloat162float(hh.y);
    __nv_bfloat162 mm = __floats2bfloat162_rn(rx, ry);
    h = *(const uint32_t*)&hh;
    m = *(const uint32_t*)&mm;
}

// ---------------------------------------------------------------------------
// One-time producers: x -> planes; w^T -> planes
// ---------------------------------------------------------------------------
__global__ __launch_bounds__(256) void cvt_x_kernel(const float* __restrict__ x)
{
    const size_t i = (size_t)blockIdx.x * 256 + threadIdx.x;   // float4 index
    float4 v = ((const float4*)x)[i];
    uint32_t h0, m0, h1, m1;
    cvt2(v.x, v.y, h0, m0);
    cvt2(v.z, v.w, h1, m1);
    ((uint2*)g_xh)[i] = make_uint2(h0, h1);
    ((uint2*)g_xm)[i] = make_uint2(m0, m1);
}

template<int R, int C, int WHICH>
__global__ __launch_bounds__(256) void transpose_kernel(const float* __restrict__ src)
{
    __shared__ float t[32][33];
    __nv_bfloat16* dh = WHICH ? g_woutTh : g_wqkvTh;
    __nv_bfloat16* dm = WHICH ? g_woutTm : g_wqkvTm;
    int c0 = blockIdx.x * 32, r0 = blockIdx.y * 32;
    #pragma unroll
    for (int i = threadIdx.y; i < 32; i += 8)
        t[i][threadIdx.x] = src[(size_t)(r0 + i) * C + c0 + threadIdx.x];
    __syncthreads();
    #pragma unroll
    for (int i = threadIdx.y; i < 32; i += 8) {
        float v = t[threadIdx.x][i];
        __nv_bfloat16 hh = __float2bfloat16(v);
        __nv_bfloat16 mm = __float2bfloat16(v - __bfloat162float(hh));
        size_t idx = (size_t)(c0 + i) * R + r0 + threadIdx.x;
        dh[idx] = hh;
        dm[idx] = mm;
    }
}

// ---------------------------------------------------------------------------
// mma.sync bf16 split GEMM, 512 threads (16 warps x 32x32 warp tiles),
// CTA tile 128x128, KC=32, cp.async double-buffered (pitch 80, conflict-free).
// Planes/buffer: A_hi@0 A_mid@10240 B_hi@20480 B_mid@30720 (40960 B).
// MODE 0: x @ w_qkv -> Q planes (*QSCALE) + K/V planes.
// MODE 1: att @ w_out + bias -> out fp32.
// ---------------------------------------------------------------------------
#define PLANE_OFS 10240u
#define GEMM_BUF  40960u
#define GEMM_DYNSMEM (2*40960)

template<int MODE>
__global__ __launch_bounds__(512, 1) void mma_gemm(
    const float* __restrict__ bias, float* __restrict__ C)
{
    extern __shared__ char sm[];
    const char* Ah = (const char*)(MODE ? g_atth : g_xh);
    const char* Am = (const char*)(MODE ? g_attm : g_xm);
    const char* Bh = (const char*)(MODE ? g_woutTh : g_wqkvTh);
    const char* Bm = (const char*)(MODE ? g_woutTm : g_wqkvTm);
    const int K = 1024;

    const int tid  = threadIdx.x;
    const int lane = tid & 31, wid = tid >> 5;
    const int warp_m = (wid >> 2) * 32;      // 0..96
    const int warp_n = (wid & 3) * 32;       // 0..96
    const int row0 = blockIdx.y * 128;
    const int col0 = blockIdx.x * 128;

    const uint32_t smb = smem_u32(sm);

    // Loader: thread -> (row r, 16B chunk q) per plane; 512 threads cover
    // 128 rows x 4 chunks exactly once per plane.
    const int r = tid >> 2, q = tid & 3;
    const char* pAh = Ah + ((size_t)(row0 + r) * K) * 2 + q * 16;
    const char* pAm = Am + ((size_t)(row0 + r) * K) * 2 + q * 16;
    const char* pBh = Bh + ((size_t)(col0 + r) * K) * 2 + q * 16;
    const char* pBm = Bm + ((size_t)(col0 + r) * K) * 2 + q * 16;
    const uint32_t stD = (uint32_t)(r * 80 + q * 16);

    const uint32_t lm_row = (uint32_t)(lane & 15);
    const uint32_t lm_col = (lane & 16) ? 16u : 0u;
    const uint32_t aofs = (uint32_t)(warp_m + lm_row) * 80 + lm_col;
    const uint32_t bofs = 20480u + (uint32_t)(warp_n + lm_row) * 80 + lm_col;

    float acc[2][4][4];
    #pragma unroll
    for (int t = 0; t < 2; t++)
        #pragma unroll
        for (int j = 0; j < 4; j++)
            #pragma unroll
            for (int rr = 0; rr < 4; rr++) acc[t][j][rr] = 0.f;

    // issue chunk c into buffer
    auto issue = [&](uint32_t bufb, int c) {
        const size_t o = (size_t)c * 64;     // 32 elems * 2B
        cpa16(bufb + stD,             pAh + o);
        cpa16(bufb + stD + PLANE_OFS, pAm + o);
        cpa16(bufb + stD + 20480u,    pBh + o);
        cpa16(bufb + stD + 30720u,    pBm + o);
    };

    issue(smb, 0);
    CPA_COMMIT();

    for (int c = 0; c < 32; ++c) {
        const uint32_t buf = smb + (uint32_t)(c & 1) * GEMM_BUF;
        CPA_WAIT0();
        __syncthreads();
        if (c < 31) {
            issue(smb + (uint32_t)((c + 1) & 1) * GEMM_BUF, c + 1);
            CPA_COMMIT();
        }
        #pragma unroll
        for (int ks = 0; ks < 2; ++ks) {
            uint32_t Af[2][4], Amf[2][4], Bf[2][4], Bmf[2][4];
            #pragma unroll
            for (int t = 0; t < 2; t++) {
                uint32_t ad = buf + aofs + (uint32_t)(t * 16 * 80 + ks * 32);
                ldsm4(Af[t], ad);
                ldsm4(Amf[t], ad + PLANE_OFS);
            }
            #pragma unroll
            for (int u = 0; u < 2; u++) {
                uint32_t bd = buf + bofs + (uint32_t)(u * 16 * 80 + ks * 32);
                ldsm4(Bf[u], bd);
                ldsm4(Bmf[u], bd + PLANE_OFS);
            }
            #pragma unroll
            for (int t = 0; t < 2; t++)
                #pragma unroll
                for (int j = 0; j < 4; j++) {
                    const int u = j >> 1, s = j & 1;
                    mma_bf16(acc[t][j], Af[t],  Bf[u][s],  Bf[u][s + 2]);
                    mma_bf16(acc[t][j], Af[t],  Bmf[u][s], Bmf[u][s + 2]);
                    mma_bf16(acc[t][j], Amf[t], Bf[u][s],  Bf[u][s + 2]);
                }
        }
    }

    const int g  = lane >> 2;
    const int tg = lane & 3;
    #pragma unroll
    for (int t = 0; t < 2; t++) {
        const int rowA = row0 + warp_m + t * 16 + g;
        #pragma unroll
        for (int j = 0; j < 4; j++) {
            const int cg = col0 + warp_n + j * 8 + 2 * tg;
            float2 lo = make_float2(acc[t][j][0], acc[t][j][1]);
            float2 hi = make_float2(acc[t][j][2], acc[t][j][3]);
            if (MODE == 0) {
                const int part = cg >> 10;
                const int w = cg & 1023;
                const int h = w >> 6, d = w & 63;
                #pragma unroll
                for (int rr = 0; rr < 2; rr++) {
                    const int row = rowA + rr * 8;
                    const int b = row >> 11, n = row & (SEQ - 1);
                    const size_t idx = ((size_t)((b * HEADS + h) * SEQ + n)) * DHEAD + d;
                    float2 v = rr ? hi : lo;
                    uint32_t ph, pm;
                    if (part == 0) {
                        cvt2(v.x * QSCALE, v.y * QSCALE, ph, pm);
                        ((uint32_t*)g_qh)[idx >> 1] = ph;
                        ((uint32_t*)g_qm)[idx >> 1] = pm;
                    } else if (part == 1) {
                        cvt2(v.x, v.y, ph, pm);
                        ((uint32_t*)g_kh)[idx >> 1] = ph;
                        ((uint32_t*)g_km)[idx >> 1] = pm;
                    } else {
                        cvt2(v.x, v.y, ph, pm);
                        ((uint32_t*)g_vh)[idx >> 1] = ph;
                        ((uint32_t*)g_vm)[idx >> 1] = pm;
                    }
                }
            } else {
                const float bx = bias[cg], by = bias[cg + 1];
                lo.x += bx; lo.y += by;
                hi.x += bx; hi.y += by;
                *(float2*)(C + (size_t)rowA * DIM + cg) = lo;
                *(float2*)(C + (size_t)(rowA + 8) * DIM + cg) = hi;
            }
        }
    }
}

// ---------------------------------------------------------------------------
// Tensor-core flash attention. 256 threads (8 warps x 16 Q rows), 2 CTAs/SM.
// Q planes resident in smem (ldsm per chunk); KV chunks of 64 via cp.async
// double buffer. Pitch 128 with XOR-row swizzle (chunk ^= row&7): conflict-free.
// Smem: Qh@0 (16K) Qm@16384 | buf b at 32768+b*32768: Kh+0 Km+8192 Vh+16384 Vm+24576.
// ---------------------------------------------------------------------------
#define ATT_SMEM (32768 + 2*32768)

__global__ __launch_bounds__(256, 2) void attn_mma_kernel()
{
    extern __shared__ char sm[];
    const uint32_t smb = smem_u32(sm);
    const int tid  = threadIdx.x;
    const int lane = tid & 31, wid = tid >> 5;
    const int bh = blockIdx.y;
    const int q0 = blockIdx.x * 128;
    const int warp_m = wid * 16;

    const size_t qbase  = ((size_t)bh * SEQ + q0) * DHEAD;
    const size_t kvbase = (size_t)bh * SEQ * DHEAD;

    const int g  = lane >> 2, tg = lane & 3;
    const uint32_t lm_row  = (uint32_t)(lane & 15);
    const uint32_t half    = (lane & 16) ? 1u : 0u;

    // ---- prologue: Q planes -> smem (group), KV chunk 0 (group) ----
    {
        #pragma unroll
        for (int i = 0; i < 4; i++) {
            const int idx = i * 256 + tid;
            const int qr = idx >> 3, ch = idx & 7;
            const uint32_t dst = (uint32_t)(qr * 128 + ((ch ^ (qr & 7)) * 16));
            const size_t so = (qbase + (size_t)qr * 64 + ch * 8) * 2;
            cpa16(smb + dst,          (const char*)g_qh + so);
            cpa16(smb + 16384u + dst, (const char*)g_qm + so);
        }
        CPA_COMMIT();
    }

    // KV loader: thread -> row kr (0..63), two 16B chunks 2*q2, 2*q2+1 per plane
    const int kr = tid >> 2, q2 = tid & 3;
    const size_t ksrc = (kvbase + (size_t)kr * DHEAD) * 2;   // byte offset
    const uint32_t d0 = (uint32_t)(kr * 128 + (((2*q2)     ^ (kr & 7)) * 16));
    const uint32_t d1 = (uint32_t)(kr * 128 + (((2*q2 + 1) ^ (kr & 7)) * 16));
    const uint32_t s0 = (uint32_t)(2*q2) * 16, s1 = (uint32_t)(2*q2+1) * 16;

    auto issue_kv = [&](uint32_t bufb, int c) {
        const size_t o = ksrc + (size_t)c * 8192;            // 64 rows * 64 el * 2B
        cpa16(bufb + d0,          (const char*)g_kh + o + s0);
        cpa16(bufb + d1,          (const char*)g_kh + o + s1);
        cpa16(bufb + 8192u  + d0, (const char*)g_km + o + s0);
        cpa16(bufb + 8192u  + d1, (const char*)g_km + o + s1);
        cpa16(bufb + 16384u + d0, (const char*)g_vh + o + s0);
        cpa16(bufb + 16384u + d1, (const char*)g_vh + o + s1);
        cpa16(bufb + 24576u + d0, (const char*)g_vm + o + s0);
        cpa16(bufb + 24576u + d1, (const char*)g_vm + o + s1);
    };
    issue_kv(smb + 32768u, 0);
    CPA_COMMIT();

    float m0 = -1e30f, m1 = -1e30f, l0 = 0.f, l1 = 0.f;
    float o[8][4];
    #pragma unroll
    for (int u = 0; u < 8; u++)
        #pragma unroll
        for (int rr = 0; rr < 4; rr++) o[u][rr] = 0.f;

    // Q ldsm address pieces (row = warp_m + lm_row; (row&7) == (lm_row&7))
    const uint32_t qrow = (uint32_t)(warp_m + lm_row);
    const uint32_t qsw  = (lm_row & 7);

    for (int c = 0; c < 32; ++c) {
        const uint32_t buf = smb + 32768u + (uint32_t)(c & 1) * 32768u;
        CPA_WAIT0();
        __syncthreads();
        if (c < 31) {
            issue_kv(smb + 32768u + (uint32_t)((c + 1) & 1) * 32768u, c + 1);
            CPA_COMMIT();
        }

        // ---- S = Q @ K^T (3-pass) ----
        float s[8][4];
        #pragma unroll
        for (int j = 0; j < 8; j++)
            #pragma unroll
            for (int rr = 0; rr < 4; rr++) s[j][rr] = 0.f;

        #pragma unroll
        for (int ks = 0; ks < 4; ks++) {
            const uint32_t qch = (uint32_t)(ks * 2) + half;
            const uint32_t qa = smb + qrow * 128 + ((qch ^ qsw) * 16);
            uint32_t ah[4], am[4];
            ldsm4(ah, qa);
            ldsm4(am, qa + 16384u);
            #pragma unroll
            for (int u = 0; u < 4; u++) {
                const uint32_t krow = (uint32_t)(u * 16) + lm_row;
                const uint32_t ka = buf + krow * 128 + ((qch ^ (krow & 7)) * 16);
                uint32_t bh4[4], bm4[4];
                ldsm4(bh4, ka);
                ldsm4(bm4, ka + 8192u);
                #pragma unroll
                for (int ss = 0; ss < 2; ss++) {
                    const int j = 2*u + ss;
                    mma_bf16(s[j], ah, bh4[ss], bh4[ss + 2]);
                    mma_bf16(s[j], ah, bm4[ss], bm4[ss + 2]);
                    mma_bf16(s[j], am, bh4[ss], bh4[ss + 2]);
                }
            }
        }

        // ---- online softmax (base-2) ----
        float mlo = s[0][0], mhi = s[0][2];
        #pragma unroll
        for (int j = 0; j < 8; j++) {
            mlo = fmaxf(mlo, fmaxf(s[j][0], s[j][1]));
            mhi = fmaxf(mhi, fmaxf(s[j][2], s[j][3]));
        }
        mlo = fmaxf(mlo, __shfl_xor_sync(0xffffffffu, mlo, 1));
        mlo = fmaxf(mlo, __shfl_xor_sync(0xffffffffu, mlo, 2));
        mhi = fmaxf(mhi, __shfl_xor_sync(0xffffffffu, mhi, 1));
        mhi = fmaxf(mhi, __shfl_xor_sync(0xffffffffu, mhi, 2));
        const float mn0 = fmaxf(m0, mlo), mn1 = fmaxf(m1, mhi);
        const float al0 = ex2(m0 - mn0),  al1 = ex2(m1 - mn1);
        m0 = mn0; m1 = mn1;

        float sum0 = 0.f, sum1 = 0.f;
        #pragma unroll
        for (int j = 0; j < 8; j++) {
            s[j][0] = ex2(s[j][0] - mn0); sum0 += s[j][0];
            s[j][1] = ex2(s[j][1] - mn0); sum0 += s[j][1];
            s[j][2] = ex2(s[j][2] - mn1); sum1 += s[j][2];
            s[j][3] = ex2(s[j][3] - mn1); sum1 += s[j][3];
        }
        sum0 += __shfl_xor_sync(0xffffffffu, sum0, 1);
        sum0 += __shfl_xor_sync(0xffffffffu, sum0, 2);
        sum1 += __shfl_xor_sync(0xffffffffu, sum1, 1);
        sum1 += __shfl_xor_sync(0xffffffffu, sum1, 2);
        l0 = l0 * al0 + sum0;
        l1 = l1 * al1 + sum1;

        #pragma unroll
        for (int u = 0; u < 8; u++) {
            o[u][0] *= al0; o[u][1] *= al0;
            o[u][2] *= al1; o[u][3] *= al1;
        }

        // ---- O += P @ V ----
        #pragma unroll
        for (int kk = 0; kk < 4; kk++) {
            uint32_t pah[4], pam[4];
            cvt2(s[2*kk][0],   s[2*kk][1],   pah[0], pam[0]);
            cvt2(s[2*kk][2],   s[2*kk][3],   pah[1], pam[1]);
            cvt2(s[2*kk+1][0], s[2*kk+1][1], pah[2], pam[2]);
            cvt2(s[2*kk+1][2], s[2*kk+1][3], pah[3], pam[3]);
            const uint32_t vrow = (uint32_t)(kk * 16) + lm_row;
            const uint32_t vbase = buf + 16384u + vrow * 128;
            const uint32_t vsw = (vrow & 7);
            #pragma unroll
            for (int u = 0; u < 4; u++) {
                const uint32_t vch = (uint32_t)(u * 2) + half;
                const uint32_t va = vbase + ((vch ^ vsw) * 16);
                uint32_t vh[4], vm[4];
                ldsm4t(vh, va);
                ldsm4t(vm, va + 8192u);
                mma_bf16(o[2*u],   pah, vh[0], vh[1]);
                mma_bf16(o[2*u],   pah, vm[0], vm[1]);
                mma_bf16(o[2*u],   pam, vh[0], vh[1]);
                mma_bf16(o[2*u+1], pah, vh[2], vh[3]);
                mma_bf16(o[2*u+1], pah, vm[2], vm[3]);
                mma_bf16(o[2*u+1], pam, vh[2], vh[3]);
            }
        }
    }

    // ---- epilogue: O/l -> att planes ----
    const float inv0 = 1.f / l0, inv1 = 1.f / l1;
    const int bb = bh >> 4, hh = bh & 15;
    const int row_lo = q0 + warp_m + g;
    const size_t e0 = ((size_t)(bb * SEQ + row_lo)) * DIM + hh * DHEAD;
    const size_t e1 = e0 + (size_t)8 * DIM;
    #pragma unroll
    for (int u = 0; u < 8; u++) {
        const int cg = u * 8 + 2 * tg;
        uint32_t ph, pm;
        cvt2(o[u][0] * inv0, o[u][1] * inv0, ph, pm);
        ((uint32_t*)g_atth)[(e0 + cg) >> 1] = ph;
        ((uint32_t*)g_attm)[(e0 + cg) >> 1] = pm;
        cvt2(o[u][2] * inv1, o[u][3] * inv1, ph, pm);
        ((uint32_t*)g_atth)[(e1 + cg) >> 1] = ph;
        ((uint32_t*)g_attm)[(e1 + cg) >> 1] = pm;
    }
}

// ---------------------------------------------------------------------------
extern "C" void kernel_launch(void* const* d_in, const int* in_sizes, int n_in,
                              void* d_out, int out_size)
{
    const float* x     = (const float*)d_in[0];
    const float* w_qkv = (const float*)d_in[1];
    const float* w_out = (const float*)d_in[2];
    const float* b_out = (const float*)d_in[3];
    float* out = (float*)d_out;
    (void)in_sizes; (void)n_in; (void)out_size;

    cudaFuncSetAttribute(mma_gemm<0>, cudaFuncAttributeMaxDynamicSharedMemorySize, GEMM_DYNSMEM);
    cudaFuncSetAttribute(mma_gemm<1>, cudaFuncAttributeMaxDynamicSharedMemorySize, GEMM_DYNSMEM);
    cudaFuncSetAttribute(attn_mma_kernel, cudaFuncAttributeMaxDynamicSharedMemorySize, ATT_SMEM);

    // One-time conversions
    cvt_x_kernel<<<MTOT * DIM / 4 / 256, 256>>>(x);
    transpose_kernel<DIM, QKVN, 0><<<dim3(QKVN / 32, DIM / 32), dim3(32, 8)>>>(w_qkv);
    transpose_kernel<DIM, DIM, 1><<<dim3(DIM / 32, DIM / 32), dim3(32, 8)>>>(w_out);

    // QKV projection -> Q/K/V bf16 planes
    dim3 gq(QKVN / 128, MTOT / 128);
    mma_gemm<0><<<gq, 512, GEMM_DYNSMEM>>>(nullptr, nullptr);

    // Tensor-core flash attention -> att planes
    dim3 ga(SEQ / 128, BATCH * HEADS);
    attn_mma_kernel<<<ga, 256, ATT_SMEM>>>();

    // Output projection + bias
    dim3 go(DIM / 128, MTOT / 128);
    mma_gemm<1><<<go, 512, GEMM_DYNSMEM>>>(b_out, out);
}